// round 12
// baseline (speedup 1.0000x reference)
#include <cuda_runtime.h>
#include <math.h>
#include <stdint.h>

#define Bn 32
#define Nn 262144
#define Gn 256
#define SEGSZ 2048              // elements per warp-segment
#define SEGPB (Nn / SEGSZ)      // 128 segments per batch
#define NSEG (Bn * SEGPB)       // 4096 segments
#define NWARP 8                 // warps per block (hist)
#define NWARP2 4                // warps per block (scatter)
#define CHUNK 16384
#define NBLK ((Bn * Nn) / CHUNK)   // 512

// ---------------- scratch (device globals; no allocation) ----------------
__device__ unsigned g_cnt[NSEG][Gn];   // counts -> within-batch exclusive prefix (after k_scan)
__device__ unsigned g_base[Bn][Gn];    // group base offset within batch
__device__ unsigned g_tot[Bn][Gn];     // group totals
__device__ float    g_sorted[Bn * Nn]; // stable-partitioned pr (n-order within group)
__device__ float4   g_SMM[Bn * Gn];    // per-group (sum, min, max, -)
__device__ float4   g_P[Bn * Gn];      // per-group (mn', rng, df, f0')

__device__ __forceinline__ bool bit_isnan(float f) {
    return (__float_as_uint(f) << 1) > 0xFF000000u;
}
__device__ __forceinline__ bool bit_iszero(float f) {
    return (__float_as_uint(f) << 1) == 0u;
}
__device__ __forceinline__ bool bit_nonfinite(float f) {
    return (__float_as_uint(f) << 1) >= 0xFF000000u;
}

// ---------------- kernel 1: per-segment histogram (warp-private) ---------
__global__ __launch_bounds__(256) void k_hist(const int* __restrict__ vr) {
    __shared__ unsigned s_h[NWARP][Gn];
    int t = threadIdx.x, w = t >> 5, l = t & 31;
    unsigned lt = (1u << l) - 1u;

#pragma unroll
    for (int i = l; i < Gn; i += 32) s_h[w][i] = 0u;
    __syncwarp();

    long seg = (long)blockIdx.x * NWARP + w;
    const int4* __restrict__ src = (const int4*)(vr + seg * SEGSZ);

#pragma unroll 2
    for (int r = 0; r < SEGSZ / 128; ++r) {
        int4 v = src[r * 32 + l];
        int gv[4] = {v.x, v.y, v.z, v.w};
#pragma unroll
        for (int e = 0; e < 4; ++e) {
            unsigned m = __match_any_sync(0xFFFFFFFFu, gv[e]);
            if ((m & lt) == 0u) s_h[w][gv[e]] += __popc(m);
        }
    }
    __syncwarp();

#pragma unroll
    for (int i = l; i < Gn; i += 32) g_cnt[seg][i] = s_h[w][i];
}

// ---------------- kernel 2: scans (per-batch) ----------------------------
__global__ __launch_bounds__(Gn) void k_scan() {
    int b = blockIdx.x;
    int g = threadIdx.x;

    unsigned run = 0;
#pragma unroll 8
    for (int s = 0; s < SEGPB; ++s) {
        int idx = b * SEGPB + s;
        unsigned c = g_cnt[idx][g];
        g_cnt[idx][g] = run;          // exclusive prefix within batch, per group
        run += c;
    }
    g_tot[b][g] = run;

    __shared__ unsigned sh[Gn];
    sh[g] = run;
    __syncthreads();
    for (int d = 1; d < Gn; d <<= 1) {
        unsigned x = (g >= d) ? sh[g - d] : 0u;
        __syncthreads();
        sh[g] += x;
        __syncthreads();
    }
    g_base[b][g] = sh[g] - run;       // exclusive scan over groups
}

// ---------------- kernel 3: stable scatter (precomputed-dst staging) -----
// per-warp smem: s_val[2048]f (8KB) + s_dst[2048]u32 (8KB) + s_lrun[256] + s_K[256]
#define SCAT_SMEM (NWARP2 * (SEGSZ * 4 + SEGSZ * 4 + Gn * 4 + Gn * 4))   // 72KB

__global__ __launch_bounds__(128) void k_scatter(const float* __restrict__ pr,
                                                 const int* __restrict__ vr) {
    extern __shared__ unsigned char sm[];
    int t = threadIdx.x, w = t >> 5, l = t & 31;
    unsigned lt = (1u << l) - 1u;

    float*    s_val  = (float*)sm + (long)w * SEGSZ;
    unsigned* s_dst  = (unsigned*)(sm + NWARP2 * SEGSZ * 4) + w * SEGSZ;
    unsigned* s_lrun = (unsigned*)(sm + NWARP2 * SEGSZ * 8) + w * Gn;
    unsigned* s_K    = (unsigned*)(sm + NWARP2 * SEGSZ * 8 + NWARP2 * Gn * 4) + w * Gn;

    long seg = (long)blockIdx.x * NWARP2 + w;
    int b    = (int)(seg >> 7);       // seg / SEGPB
    int sidx = (int)(seg & (SEGPB - 1));
    bool last = (sidx == SEGPB - 1);

    // ---- phase 0: per-group local counts (prefix-row diff) + warp scan ----
    const uint4* preR  = (const uint4*)g_cnt[seg];
    const uint4* nxtR  = last ? (const uint4*)g_tot[b] : (const uint4*)g_cnt[seg + 1];
    const uint4* gbR   = (const uint4*)g_base[b];

    unsigned pre[8], cnt[8], gb[8];
#pragma unroll
    for (int h = 0; h < 2; ++h) {
        uint4 a = preR[l * 2 + h], c = nxtR[l * 2 + h], d = gbR[l * 2 + h];
        pre[h*4+0] = a.x; pre[h*4+1] = a.y; pre[h*4+2] = a.z; pre[h*4+3] = a.w;
        cnt[h*4+0] = c.x - a.x; cnt[h*4+1] = c.y - a.y;
        cnt[h*4+2] = c.z - a.z; cnt[h*4+3] = c.w - a.w;
        gb[h*4+0] = d.x; gb[h*4+1] = d.y; gb[h*4+2] = d.z; gb[h*4+3] = d.w;
    }
    unsigned lsum = 0;
#pragma unroll
    for (int k = 0; k < 8; ++k) lsum += cnt[k];
    unsigned sc = lsum;
#pragma unroll
    for (int d = 1; d < 32; d <<= 1) {
        unsigned v = __shfl_up_sync(0xFFFFFFFFu, sc, d);
        if (l >= d) sc += v;
    }
    unsigned running = sc - lsum;     // exclusive
#pragma unroll
    for (int k = 0; k < 8; ++k) {
        int g = l * 8 + k;
        s_lrun[g] = running;                       // lbase
        s_K[g]    = gb[k] + pre[k] - running;      // dest = K[g] + slot
        running  += cnt[k];
    }
    __syncwarp();

    // ---- phase A: rank + stage value AND precomputed dst, stable n-order --
    const int*   __restrict__ vs = vr + seg * SEGSZ;
    const float* __restrict__ ps = pr + seg * SEGSZ;
    volatile unsigned* vrun = s_lrun;   // leader-only access; volatile pins order

#pragma unroll 4
    for (int r = 0; r < SEGSZ / 32; ++r) {
        int   g = vs[r * 32 + l];
        float p = ps[r * 32 + l];
        unsigned m = __match_any_sync(0xFFFFFFFFu, g);
        unsigned lr = __popc(m & lt);
        int leader = __ffs(m) - 1;
        unsigned cur = 0;
        if (lr == 0u) cur = vrun[g];
        cur = __shfl_sync(m, cur, leader);
        unsigned slot = cur + lr;
        s_val[slot] = p;
        s_dst[slot] = s_K[g] + slot;
        if (lr == 0u) vrun[g] = cur + __popc(m);
    }
    __syncwarp();

    // ---- phase B: linear sweep, 4 slots/thread, run-coalesced stores ----
    float* __restrict__ bdst = g_sorted + (long)b * Nn;
#pragma unroll 4
    for (int it = 0; it < SEGSZ / 128; ++it) {
        int s = it * 128 + l * 4;
        float4 v4 = *(const float4*)(s_val + s);
        uint4  d4 = *(const uint4*)(s_dst + s);
        bdst[d4.x] = v4.x;
        bdst[d4.y] = v4.y;
        bdst[d4.z] = v4.z;
        bdst[d4.w] = v4.w;
    }
}

// ---------------- kernel 4: sequential fold (depth-4 ring pipeline) ------
__device__ __forceinline__ void fold8(float4* q, float& acc, float& mn, float& mx) {
#pragma unroll
    for (int j = 0; j < 8; ++j) {
        acc = __fadd_rn(acc, q[j].x);
        acc = __fadd_rn(acc, q[j].y);
        acc = __fadd_rn(acc, q[j].z);
        acc = __fadd_rn(acc, q[j].w);
        mn = fminf(mn, fminf(fminf(q[j].x, q[j].y), fminf(q[j].z, q[j].w)));
        mx = fmaxf(mx, fmaxf(fmaxf(q[j].x, q[j].y), fmaxf(q[j].z, q[j].w)));
    }
}

__device__ __forceinline__ void load8(float4* q, const float* p) {
#pragma unroll
    for (int j = 0; j < 8; ++j) q[j] = *(const float4*)(p + j * 4);
}

__global__ __launch_bounds__(32) void k_fold() {
    int gid = blockIdx.x * 32 + threadIdx.x;   // 0..8191
    int b = gid >> 8, g = gid & 255;

    unsigned cnt  = g_tot[b][g];
    const float* __restrict__ src = g_sorted + (long)b * Nn + g_base[b][g];

    float acc = 0.0f;
    float mn =  __int_as_float(0x7F800000);    // +inf
    float mx = -__int_as_float(0x7F800000);    // -inf

    unsigned i = 0;
    // scalar head until 16B aligned (order-preserving)
    while (i < cnt && ((((uintptr_t)(src + i)) & 15u) != 0u)) {
        float a = src[i];
        acc = __fadd_rn(acc, a);
        mn = fminf(mn, a); mx = fmaxf(mx, a);
        ++i;
    }

    // depth-4 ring: 32 LDG.128 in flight; folds strictly in batch order
    unsigned nb = (cnt - i) / 32;              // number of 32-elem batches
    float4 b0[8], b1[8], b2[8], b3[8];
    if (nb > 0) load8(b0, src + i);
    if (nb > 1) load8(b1, src + i + 32);
    if (nb > 2) load8(b2, src + i + 64);
    if (nb > 3) load8(b3, src + i + 96);

    unsigned bi = 0;
    for (; bi + 4 <= nb; bi += 4) {
        fold8(b0, acc, mn, mx);
        if (bi + 4 < nb) load8(b0, src + i + (bi + 4) * 32);
        fold8(b1, acc, mn, mx);
        if (bi + 5 < nb) load8(b1, src + i + (bi + 5) * 32);
        fold8(b2, acc, mn, mx);
        if (bi + 6 < nb) load8(b2, src + i + (bi + 6) * 32);
        fold8(b3, acc, mn, mx);
        if (bi + 7 < nb) load8(b3, src + i + (bi + 7) * 32);
    }
    unsigned rem = nb - bi;                    // 0..3, slots 0..2 in order
    if (rem >= 1) fold8(b0, acc, mn, mx);
    if (rem >= 2) fold8(b1, acc, mn, mx);
    if (rem >= 3) fold8(b2, acc, mn, mx);
    i += nb * 32;

    for (; i + 4 <= cnt; i += 4) {
        float4 q = *(const float4*)(src + i);
        acc = __fadd_rn(acc, q.x);
        acc = __fadd_rn(acc, q.y);
        acc = __fadd_rn(acc, q.z);
        acc = __fadd_rn(acc, q.w);
        mn = fminf(mn, fminf(fminf(q.x, q.y), fminf(q.z, q.w)));
        mx = fmaxf(mx, fmaxf(fmaxf(q.x, q.y), fmaxf(q.z, q.w)));
    }
    for (; i < cnt; ++i) {
        float a = src[i];
        acc = __fadd_rn(acc, a);
        mn = fminf(mn, a); mx = fmaxf(mx, a);
    }

    g_SMM[gid] = make_float4(acc, mn, mx, 0.0f);
}

// ---------------- kernel 5: sort + per-group affine params ---------------
__global__ __launch_bounds__(Gn) void k_params(const float* __restrict__ inp_means,
                                               const float* __restrict__ W) {
    __shared__ float skey[Gn];
    __shared__ int   sid[Gn];
    __shared__ float f0u[Gn];
    __shared__ float f1u[Gn];

    int b = blockIdx.x;
    int g = threadIdx.x;
    int o = b * Gn + g;

    float4 smm = g_SMM[o];
    unsigned cnt = g_tot[b][g];
    bool any = (cnt > 0u);
    float vsum = any ? smm.x : 0.0f;
    float mn = smm.y, mx = smm.z;

    float W0 = W[0], W1 = W[1];
    float vmean = __fdiv_rn(__fadd_rn(__fmul_rn(inp_means[o], W0),
                                      __fmul_rn(vsum, W1)),
                            __fadd_rn(W0, W1));

    skey[g] = vmean;
    sid[g]  = g;
    __syncthreads();

    // bitonic sort on (value, id) == jax stable argsort
    for (int k = 2; k <= Gn; k <<= 1) {
        for (int j = k >> 1; j > 0; j >>= 1) {
            int ixj = g ^ j;
            if (ixj > g) {
                float a = skey[g], c = skey[ixj];
                int ia = sid[g], ic = sid[ixj];
                bool up = ((g & k) == 0);
                bool gt = (a > c) || (a == c && ia > ic);
                if (gt == up) {
                    skey[g] = c; skey[ixj] = a;
                    sid[g] = ic; sid[ixj] = ia;
                }
            }
            __syncthreads();
        }
    }

    float vsr   = skey[g];
    float vprev = (g == 0)      ? vsr : skey[g - 1];
    float vnext = (g == Gn - 1) ? __fmul_rn(vsr, 2.0f) : skey[g + 1];
    float f0 = __fdiv_rn(__fadd_rn(vprev, vsr), 1.999f);
    float f1 = __fdiv_rn(__fadd_rn(vsr, vnext), 2.001f);
    f0u[sid[g]] = f0;
    f1u[sid[g]] = f1;
    __syncthreads();

    bool ns = (mn == mx);   // empty group: inf == -inf -> false (matches ref)

    float mn2, mx2, f02, f12;
    if (!any) { mn2 = 0.0f; mx2 = 1.0f; f02 = 0.0f; f12 = 0.0f; }
    else {
        mn2 = ns ? 0.0f : mn;
        mx2 = ns ? 1.0f : mx;
        f02 = ns ? 0.0f : f0u[g];
        f12 = ns ? 1.0f : f1u[g];
    }
    float rng = __fsub_rn(mx2, mn2);
    float df  = __fsub_rn(f12, f02);
    g_P[o] = make_float4(mn2, rng, df, f02);
}

// ---------------- kernel 6: elementwise apply ----------------------------
__device__ __forceinline__ float apply_one(float p, float4 P) {
    float t1  = __fsub_rn(p, P.x);
    float t2  = __fdiv_rn(t1, P.y);
    float t3  = __fmul_rn(t2, P.z);
    float tmp = __fadd_rn(t3, P.w);
    bool bad = bit_isnan(tmp) || bit_iszero(tmp);
    float den = bad ? 1.0f : tmp;
    float r;
    asm("rcp.approx.f32 %0, %1;" : "=f"(r) : "f"(den));
    float s = __fmul_rn(p, r);
    float scale = (bad || bit_nonfinite(s)) ? 0.0f : s;
    return __fmul_rn(p, scale);
}

__global__ __launch_bounds__(256) void k_apply(const float* __restrict__ pr,
                                               const int* __restrict__ vr,
                                               float* __restrict__ out) {
    __shared__ float4 sP[Gn];
    long base = (long)blockIdx.x * CHUNK;
    int b = blockIdx.x / (Nn / CHUNK);

    int t = threadIdx.x;
    sP[t] = g_P[b * Gn + t];
    __syncthreads();

    const float4* p4 = (const float4*)(pr + base);
    const int4*   v4 = (const int4*)(vr + base);
    float4*       o4 = (float4*)(out + base);

#pragma unroll 4
    for (int it = 0; it < CHUNK / 1024; ++it) {
        float4 p = p4[it * 256 + t];
        int4   v = v4[it * 256 + t];
        float4 r;
        r.x = apply_one(p.x, sP[v.x]);
        r.y = apply_one(p.y, sP[v.y]);
        r.z = apply_one(p.z, sP[v.z]);
        r.w = apply_one(p.w, sP[v.w]);
        o4[it * 256 + t] = r;
    }
}

// ---------------- launch --------------------------------------------------
extern "C" void kernel_launch(void* const* d_in, const int* in_sizes, int n_in,
                              void* d_out, int out_size) {
    const float* pr        = (const float*)d_in[0];
    const float* inp_means = (const float*)d_in[1];
    const int*   vr        = (const int*)d_in[2];
    const float* W         = (const float*)d_in[3];
    float* out = (float*)d_out;

    static int smem_set = 0;
    if (!smem_set) {
        cudaFuncSetAttribute(k_scatter, cudaFuncAttributeMaxDynamicSharedMemorySize,
                             SCAT_SMEM);
        smem_set = 1;
    }

    k_hist<<<NSEG / NWARP, 256>>>(vr);
    k_scan<<<Bn, Gn>>>();
    k_scatter<<<NSEG / NWARP2, 128, SCAT_SMEM>>>(pr, vr);
    k_fold<<<(Bn * Gn) / 32, 32>>>();
    k_params<<<Bn, Gn>>>(inp_means, W);
    k_apply<<<NBLK, 256>>>(pr, vr, out);
}

// round 13
// speedup vs baseline: 1.1736x; 1.1736x over previous
#include <cuda_runtime.h>
#include <math.h>
#include <stdint.h>

#define Bn 32
#define Nn 262144
#define Gn 256
#define SEGSZ 2048                 // elements per warp-segment
#define SEGPB (Nn / SEGSZ)         // 128 segments per batch
#define NSEG (Bn * SEGPB)          // 4096 segments
#define NWARP 8                    // warps per block
#define CHUNK 16384
#define NCHK ((Bn * Nn) / CHUNK)   // 512 apply chunks
#define NBLKP 128                  // persistent blocks (co-resident: 96KB -> >=1/SM)
#define SEG_PER_BLK (NSEG / NBLKP) // 32
#define SEG_ITER (SEG_PER_BLK / NWARP) // 4 segments per warp
#define CHK_PER_BLK (NCHK / NBLKP) // 4

// ---------------- scratch (device globals; no allocation) ----------------
__device__ unsigned g_cnt [NSEG][Gn];  // per-segment counts (hist)
__device__ unsigned g_pref[NSEG][Gn];  // within-batch exclusive prefix (scan)
__device__ unsigned g_base[Bn][Gn];    // group base offset within batch
__device__ unsigned g_tot [Bn][Gn];    // group totals
__device__ float    g_sorted[Bn * Nn]; // stable-partitioned pr (n-order within group)
__device__ float4   g_SMM[Bn * Gn];    // per-group (sum, min, max, -)
__device__ float4   g_P[Bn * Gn];      // per-group (mn', rng, df, f0')
__device__ unsigned g_barcnt  = 0;     // software grid barrier (self-resetting)
__device__ unsigned g_barphase = 0;

#define DSMEM (NWARP * SEGSZ * 4 + NWARP * SEGSZ + NWARP * Gn * 4 + NWARP * Gn * 4) // 96KB

__device__ __forceinline__ bool bit_isnan(float f) {
    return (__float_as_uint(f) << 1) > 0xFF000000u;
}
__device__ __forceinline__ bool bit_iszero(float f) {
    return (__float_as_uint(f) << 1) == 0u;
}
__device__ __forceinline__ bool bit_nonfinite(float f) {
    return (__float_as_uint(f) << 1) >= 0xFF000000u;
}

// ---- sense-reversing grid barrier (self-resetting; graph-replay safe) ----
__device__ __forceinline__ void grid_bar() {
    __syncthreads();
    if (threadIdx.x == 0) {
        __threadfence();
        unsigned my = *((volatile unsigned*)&g_barphase);
        if (atomicAdd(&g_barcnt, 1u) == NBLKP - 1) {
            g_barcnt = 0;
            __threadfence();
            atomicAdd(&g_barphase, 1u);       // release
        } else {
            while (*((volatile unsigned*)&g_barphase) == my) __nanosleep(128);
        }
        __threadfence();
    }
    __syncthreads();
}

// ---------------- fold helpers (verbatim from R11) ------------------------
__device__ __forceinline__ void fold8(float4* q, float& acc, float& mn, float& mx) {
#pragma unroll
    for (int j = 0; j < 8; ++j) {
        acc = __fadd_rn(acc, q[j].x);
        acc = __fadd_rn(acc, q[j].y);
        acc = __fadd_rn(acc, q[j].z);
        acc = __fadd_rn(acc, q[j].w);
        mn = fminf(mn, fminf(fminf(q[j].x, q[j].y), fminf(q[j].z, q[j].w)));
        mx = fmaxf(mx, fmaxf(fmaxf(q[j].x, q[j].y), fmaxf(q[j].z, q[j].w)));
    }
}
__device__ __forceinline__ void load8(float4* q, const float* p) {
#pragma unroll
    for (int j = 0; j < 8; ++j) q[j] = *(const float4*)(p + j * 4);
}

__device__ __forceinline__ float apply_one(float p, float4 P) {
    float t1  = __fsub_rn(p, P.x);
    float t2  = __fdiv_rn(t1, P.y);
    float t3  = __fmul_rn(t2, P.z);
    float tmp = __fadd_rn(t3, P.w);
    bool bad = bit_isnan(tmp) || bit_iszero(tmp);
    float den = bad ? 1.0f : tmp;
    float r;
    asm("rcp.approx.f32 %0, %1;" : "=f"(r) : "f"(den));
    float s = __fmul_rn(p, r);
    float scale = (bad || bit_nonfinite(s)) ? 0.0f : s;
    return __fmul_rn(p, scale);
}

// ============================ fused kernel ================================
__global__ __launch_bounds__(256, 1) void k_all(const float* __restrict__ pr,
                                                const int* __restrict__ vr,
                                                const float* __restrict__ inp_means,
                                                const float* __restrict__ W,
                                                float* __restrict__ out) {
    extern __shared__ unsigned char sm[];
    int bk = blockIdx.x;
    int t = threadIdx.x, w = t >> 5, l = t & 31;
    unsigned lt = (1u << l) - 1u;

    // ---------------- phase 1: histogram (per-warp, 4 segments) ----------
    {
        unsigned* s_h = (unsigned*)sm + w * Gn;
#pragma unroll 1
        for (int it = 0; it < SEG_ITER; ++it) {
            long seg = (long)bk * SEG_PER_BLK + it * NWARP + w;
#pragma unroll
            for (int i = l; i < Gn; i += 32) s_h[i] = 0u;
            __syncwarp();
            const int4* __restrict__ src = (const int4*)(vr + seg * SEGSZ);
#pragma unroll 2
            for (int r = 0; r < SEGSZ / 128; ++r) {
                int4 v = src[r * 32 + l];
                int gv[4] = {v.x, v.y, v.z, v.w};
#pragma unroll
                for (int e = 0; e < 4; ++e) {
                    unsigned m = __match_any_sync(0xFFFFFFFFu, gv[e]);
                    if ((m & lt) == 0u) s_h[gv[e]] += __popc(m);
                }
            }
            __syncwarp();
#pragma unroll
            for (int i = l; i < Gn; i += 32) g_cnt[seg][i] = s_h[i];
            __syncwarp();
        }
    }
    grid_bar();

    // ---------------- phase 2: scans (blocks 0..31, one per batch) --------
    if (bk < Bn) {
        int b = bk;
        int g = t;
        unsigned run = 0;
#pragma unroll 8
        for (int s = 0; s < SEGPB; ++s) {
            int idx = b * SEGPB + s;
            unsigned c = g_cnt[idx][g];
            g_pref[idx][g] = run;
            run += c;
        }
        g_tot[b][g] = run;

        unsigned* sh = (unsigned*)sm;
        sh[g] = run;
        __syncthreads();
        for (int d = 1; d < Gn; d <<= 1) {
            unsigned x = (g >= d) ? sh[g - d] : 0u;
            __syncthreads();
            sh[g] += x;
            __syncthreads();
        }
        g_base[b][g] = sh[g] - run;
    }
    grid_bar();

    // ---------------- phase 3: stable scatter (verbatim R8, g_pref) -------
    {
        float*         s_val  = (float*)sm + (long)w * SEGSZ;
        unsigned char* s_gid  = sm + NWARP * SEGSZ * 4 + w * SEGSZ;
        unsigned*      s_lrun = (unsigned*)(sm + NWARP * SEGSZ * 5) + w * Gn;
        unsigned*      s_K    = (unsigned*)(sm + NWARP * SEGSZ * 5 + NWARP * Gn * 4) + w * Gn;

#pragma unroll 1
        for (int it = 0; it < SEG_ITER; ++it) {
            long seg = (long)bk * SEG_PER_BLK + it * NWARP + w;
            int b = (int)(seg >> 7);

            const uint4* preR = (const uint4*)g_pref[seg];
            const uint4* cntR = (const uint4*)g_cnt[seg];
            const uint4* gbR  = (const uint4*)g_base[b];

            unsigned pre[8], cnt[8], gb[8];
#pragma unroll
            for (int h = 0; h < 2; ++h) {
                uint4 a = preR[l * 2 + h], c = cntR[l * 2 + h], d = gbR[l * 2 + h];
                pre[h*4+0] = a.x; pre[h*4+1] = a.y; pre[h*4+2] = a.z; pre[h*4+3] = a.w;
                cnt[h*4+0] = c.x; cnt[h*4+1] = c.y; cnt[h*4+2] = c.z; cnt[h*4+3] = c.w;
                gb[h*4+0] = d.x; gb[h*4+1] = d.y; gb[h*4+2] = d.z; gb[h*4+3] = d.w;
            }
            unsigned lsum = 0;
#pragma unroll
            for (int k = 0; k < 8; ++k) lsum += cnt[k];
            unsigned sc = lsum;
#pragma unroll
            for (int d = 1; d < 32; d <<= 1) {
                unsigned v = __shfl_up_sync(0xFFFFFFFFu, sc, d);
                if (l >= d) sc += v;
            }
            unsigned running = sc - lsum;
#pragma unroll
            for (int k = 0; k < 8; ++k) {
                int g = l * 8 + k;
                s_lrun[g] = running;
                s_K[g]    = gb[k] + pre[k] - running;
                running  += cnt[k];
            }
            __syncwarp();

            const int*   __restrict__ vs = vr + seg * SEGSZ;
            const float* __restrict__ ps = pr + seg * SEGSZ;

#pragma unroll 4
            for (int r = 0; r < SEGSZ / 32; ++r) {
                int   g = vs[r * 32 + l];
                float p = ps[r * 32 + l];
                unsigned m = __match_any_sync(0xFFFFFFFFu, g);
                unsigned lr = __popc(m & lt);
                unsigned cur = s_lrun[g];
                __syncwarp();
                unsigned slot = cur + lr;
                s_val[slot] = p;
                s_gid[slot] = (unsigned char)g;
                if (lr == 0u) s_lrun[g] = cur + __popc(m);
            }
            __syncwarp();

            float* __restrict__ dst = g_sorted + (long)b * Nn;
#pragma unroll 4
            for (int r = 0; r < SEGSZ / 32; ++r) {
                int s = r * 32 + l;
                int g = s_gid[s];
                dst[s_K[g] + s] = s_val[s];
            }
            __syncwarp();
        }
    }
    grid_bar();

    // ---------------- phase 4: sequential fold (verbatim R11 ring) --------
    if (t < 64) {
        int gid = bk * 64 + t;              // 0..8191
        int b = gid >> 8, g = gid & 255;

        unsigned cnt  = g_tot[b][g];
        const float* __restrict__ src = g_sorted + (long)b * Nn + g_base[b][g];

        float acc = 0.0f;
        float mn =  __int_as_float(0x7F800000);
        float mx = -__int_as_float(0x7F800000);

        unsigned i = 0;
        while (i < cnt && ((((uintptr_t)(src + i)) & 15u) != 0u)) {
            float a = src[i];
            acc = __fadd_rn(acc, a);
            mn = fminf(mn, a); mx = fmaxf(mx, a);
            ++i;
        }

        unsigned nb = (cnt - i) / 32;
        float4 b0[8], b1[8], b2[8], b3[8];
        if (nb > 0) load8(b0, src + i);
        if (nb > 1) load8(b1, src + i + 32);
        if (nb > 2) load8(b2, src + i + 64);
        if (nb > 3) load8(b3, src + i + 96);

        unsigned bi = 0;
        for (; bi + 4 <= nb; bi += 4) {
            fold8(b0, acc, mn, mx);
            if (bi + 4 < nb) load8(b0, src + i + (bi + 4) * 32);
            fold8(b1, acc, mn, mx);
            if (bi + 5 < nb) load8(b1, src + i + (bi + 5) * 32);
            fold8(b2, acc, mn, mx);
            if (bi + 6 < nb) load8(b2, src + i + (bi + 6) * 32);
            fold8(b3, acc, mn, mx);
            if (bi + 7 < nb) load8(b3, src + i + (bi + 7) * 32);
        }
        unsigned rem = nb - bi;
        if (rem >= 1) fold8(b0, acc, mn, mx);
        if (rem >= 2) fold8(b1, acc, mn, mx);
        if (rem >= 3) fold8(b2, acc, mn, mx);
        i += nb * 32;

        for (; i + 4 <= cnt; i += 4) {
            float4 q = *(const float4*)(src + i);
            acc = __fadd_rn(acc, q.x);
            acc = __fadd_rn(acc, q.y);
            acc = __fadd_rn(acc, q.z);
            acc = __fadd_rn(acc, q.w);
            mn = fminf(mn, fminf(fminf(q.x, q.y), fminf(q.z, q.w)));
            mx = fmaxf(mx, fmaxf(fmaxf(q.x, q.y), fmaxf(q.z, q.w)));
        }
        for (; i < cnt; ++i) {
            float a = src[i];
            acc = __fadd_rn(acc, a);
            mn = fminf(mn, a); mx = fmaxf(mx, a);
        }

        g_SMM[gid] = make_float4(acc, mn, mx, 0.0f);
    }
    grid_bar();

    // ---------------- phase 5: sort + params (blocks 0..31) ---------------
    if (bk < Bn) {
        float* skey = (float*)sm;
        int*   sid  = (int*)(sm + Gn * 4);
        float* f0u  = (float*)(sm + Gn * 8);
        float* f1u  = (float*)(sm + Gn * 12);

        int b = bk;
        int g = t;
        int o = b * Gn + g;

        float4 smm = g_SMM[o];
        unsigned cnt = g_tot[b][g];
        bool any = (cnt > 0u);
        float vsum = any ? smm.x : 0.0f;
        float mn = smm.y, mx = smm.z;

        float W0 = W[0], W1 = W[1];
        float vmean = __fdiv_rn(__fadd_rn(__fmul_rn(inp_means[o], W0),
                                          __fmul_rn(vsum, W1)),
                                __fadd_rn(W0, W1));

        skey[g] = vmean;
        sid[g]  = g;
        __syncthreads();

        for (int k = 2; k <= Gn; k <<= 1) {
            for (int j = k >> 1; j > 0; j >>= 1) {
                int ixj = g ^ j;
                if (ixj > g) {
                    float a = skey[g], c = skey[ixj];
                    int ia = sid[g], ic = sid[ixj];
                    bool up = ((g & k) == 0);
                    bool gt = (a > c) || (a == c && ia > ic);
                    if (gt == up) {
                        skey[g] = c; skey[ixj] = a;
                        sid[g] = ic; sid[ixj] = ia;
                    }
                }
                __syncthreads();
            }
        }

        float vsr   = skey[g];
        float vprev = (g == 0)      ? vsr : skey[g - 1];
        float vnext = (g == Gn - 1) ? __fmul_rn(vsr, 2.0f) : skey[g + 1];
        float f0 = __fdiv_rn(__fadd_rn(vprev, vsr), 1.999f);
        float f1 = __fdiv_rn(__fadd_rn(vsr, vnext), 2.001f);
        f0u[sid[g]] = f0;
        f1u[sid[g]] = f1;
        __syncthreads();

        bool ns = (mn == mx);

        float mn2, mx2, f02, f12;
        if (!any) { mn2 = 0.0f; mx2 = 1.0f; f02 = 0.0f; f12 = 0.0f; }
        else {
            mn2 = ns ? 0.0f : mn;
            mx2 = ns ? 1.0f : mx;
            f02 = ns ? 0.0f : f0u[g];
            f12 = ns ? 1.0f : f1u[g];
        }
        float rng = __fsub_rn(mx2, mn2);
        float df  = __fsub_rn(f12, f02);
        g_P[o] = make_float4(mn2, rng, df, f02);
    }
    grid_bar();

    // ---------------- phase 6: elementwise apply (4 chunks/block) ---------
    {
        float4* sP = (float4*)sm;
#pragma unroll 1
        for (int c = 0; c < CHK_PER_BLK; ++c) {
            int chunk = bk * CHK_PER_BLK + c;
            long base = (long)chunk * CHUNK;
            int b = chunk / (Nn / CHUNK);

            __syncthreads();
            sP[t] = g_P[b * Gn + t];
            __syncthreads();

            const float4* p4 = (const float4*)(pr + base);
            const int4*   v4 = (const int4*)(vr + base);
            float4*       o4 = (float4*)(out + base);

#pragma unroll 4
            for (int it = 0; it < CHUNK / 1024; ++it) {
                float4 p = p4[it * 256 + t];
                int4   v = v4[it * 256 + t];
                float4 r;
                r.x = apply_one(p.x, sP[v.x]);
                r.y = apply_one(p.y, sP[v.y]);
                r.z = apply_one(p.z, sP[v.z]);
                r.w = apply_one(p.w, sP[v.w]);
                o4[it * 256 + t] = r;
            }
        }
    }
}

// ---------------- launch --------------------------------------------------
extern "C" void kernel_launch(void* const* d_in, const int* in_sizes, int n_in,
                              void* d_out, int out_size) {
    const float* pr        = (const float*)d_in[0];
    const float* inp_means = (const float*)d_in[1];
    const int*   vr        = (const int*)d_in[2];
    const float* W         = (const float*)d_in[3];
    float* out = (float*)d_out;

    static int smem_set = 0;
    if (!smem_set) {
        cudaFuncSetAttribute(k_all, cudaFuncAttributeMaxDynamicSharedMemorySize,
                             DSMEM);
        smem_set = 1;
    }

    k_all<<<NBLKP, 256, DSMEM>>>(pr, vr, inp_means, W, out);
}

// round 14
// speedup vs baseline: 1.5147x; 1.2907x over previous
#include <cuda_runtime.h>
#include <math.h>
#include <stdint.h>

#define Bn 32
#define Nn 262144
#define Gn 256
#define SEGSZ 2048              // elements per warp-segment
#define SEGPB (Nn / SEGSZ)      // 128 segments per batch
#define NSEG (Bn * SEGPB)       // 4096 segments
#define NWARP 8                 // warps per block (hist/scatter)
#define CHUNK 16384
#define NBLK ((Bn * Nn) / CHUNK)   // 512

// ---------------- scratch (device globals; no allocation) ----------------
__device__ unsigned g_cnt[NSEG][Gn];   // counts -> within-batch exclusive prefix (after k_scan)
__device__ unsigned g_base[Bn][Gn];    // group base offset within batch
__device__ unsigned g_tot[Bn][Gn];     // group totals
__device__ float    g_sorted[Bn * Nn]; // stable-partitioned pr (n-order within group)
__device__ float4   g_SMM[Bn * Gn];    // per-group (sum, min, max, -)
__device__ float4   g_P[Bn * Gn];      // per-group (mn', rng, df, f0')

__device__ __forceinline__ bool bit_isnan(float f) {
    return (__float_as_uint(f) << 1) > 0xFF000000u;
}
__device__ __forceinline__ bool bit_iszero(float f) {
    return (__float_as_uint(f) << 1) == 0u;
}
__device__ __forceinline__ bool bit_nonfinite(float f) {
    return (__float_as_uint(f) << 1) >= 0xFF000000u;
}

// ---------------- kernel 1: per-segment histogram (warp-private) ---------
__global__ __launch_bounds__(256) void k_hist(const int* __restrict__ vr) {
    __shared__ unsigned s_h[NWARP][Gn];
    int t = threadIdx.x, w = t >> 5, l = t & 31;
    unsigned lt = (1u << l) - 1u;

#pragma unroll
    for (int i = l; i < Gn; i += 32) s_h[w][i] = 0u;
    __syncwarp();

    long seg = (long)blockIdx.x * NWARP + w;
    const int4* __restrict__ src = (const int4*)(vr + seg * SEGSZ);

#pragma unroll 2
    for (int r = 0; r < SEGSZ / 128; ++r) {
        int4 v = src[r * 32 + l];
        int gv[4] = {v.x, v.y, v.z, v.w};
#pragma unroll
        for (int e = 0; e < 4; ++e) {
            unsigned m = __match_any_sync(0xFFFFFFFFu, gv[e]);
            if ((m & lt) == 0u) s_h[w][gv[e]] += __popc(m);
        }
    }
    __syncwarp();

#pragma unroll
    for (int i = l; i < Gn; i += 32) g_cnt[seg][i] = s_h[w][i];
}

// ---------------- kernel 2: scans (per-batch) ----------------------------
__global__ __launch_bounds__(Gn) void k_scan() {
    int b = blockIdx.x;
    int g = threadIdx.x;

    unsigned run = 0;
#pragma unroll 8
    for (int s = 0; s < SEGPB; ++s) {
        int idx = b * SEGPB + s;
        unsigned c = g_cnt[idx][g];
        g_cnt[idx][g] = run;          // exclusive prefix within batch, per group
        run += c;
    }
    g_tot[b][g] = run;

    __shared__ unsigned sh[Gn];
    sh[g] = run;
    __syncthreads();
    for (int d = 1; d < Gn; d <<= 1) {
        unsigned x = (g >= d) ? sh[g - d] : 0u;
        __syncthreads();
        sh[g] += x;
        __syncthreads();
    }
    g_base[b][g] = sh[g] - run;       // exclusive scan over groups
}

// ---------------- dummy kernel: shifts ncu capture slot onto k_scatter ---
__global__ void k_nop() {}

// ---------------- kernel 3: stable scatter via smem reorder --------------
#define SCAT_SMEM (NWARP * SEGSZ * 4 + NWARP * SEGSZ + NWARP * Gn * 4 + NWARP * Gn * 4)

__global__ __launch_bounds__(256) void k_scatter(const float* __restrict__ pr,
                                                 const int* __restrict__ vr) {
    extern __shared__ unsigned char sm[];
    int t = threadIdx.x, w = t >> 5, l = t & 31;
    unsigned lt = (1u << l) - 1u;

    float*         s_val  = (float*)sm + (long)w * SEGSZ;
    unsigned char* s_gid  = sm + NWARP * SEGSZ * 4 + w * SEGSZ;
    unsigned*      s_lrun = (unsigned*)(sm + NWARP * SEGSZ * 5) + w * Gn;
    unsigned*      s_K    = (unsigned*)(sm + NWARP * SEGSZ * 5 + NWARP * Gn * 4) + w * Gn;

    long seg = (long)blockIdx.x * NWARP + w;
    int b    = (int)(seg >> 7);       // seg / SEGPB
    int sidx = (int)(seg & (SEGPB - 1));
    bool last = (sidx == SEGPB - 1);

    // ---- phase 0: per-group local counts (prefix-row diff) + warp scan ----
    const uint4* preR  = (const uint4*)g_cnt[seg];
    const uint4* nxtR  = last ? (const uint4*)g_tot[b] : (const uint4*)g_cnt[seg + 1];
    const uint4* gbR   = (const uint4*)g_base[b];

    unsigned pre[8], cnt[8], gb[8];
#pragma unroll
    for (int h = 0; h < 2; ++h) {
        uint4 a = preR[l * 2 + h], c = nxtR[l * 2 + h], d = gbR[l * 2 + h];
        pre[h*4+0] = a.x; pre[h*4+1] = a.y; pre[h*4+2] = a.z; pre[h*4+3] = a.w;
        cnt[h*4+0] = c.x - a.x; cnt[h*4+1] = c.y - a.y;
        cnt[h*4+2] = c.z - a.z; cnt[h*4+3] = c.w - a.w;
        gb[h*4+0] = d.x; gb[h*4+1] = d.y; gb[h*4+2] = d.z; gb[h*4+3] = d.w;
    }
    unsigned lsum = 0;
#pragma unroll
    for (int k = 0; k < 8; ++k) lsum += cnt[k];
    unsigned sc = lsum;
#pragma unroll
    for (int d = 1; d < 32; d <<= 1) {
        unsigned v = __shfl_up_sync(0xFFFFFFFFu, sc, d);
        if (l >= d) sc += v;
    }
    unsigned running = sc - lsum;     // exclusive
#pragma unroll
    for (int k = 0; k < 8; ++k) {
        int g = l * 8 + k;
        s_lrun[g] = running;                       // lbase
        s_K[g]    = gb[k] + pre[k] - running;      // dest = K[g] + slot
        running  += cnt[k];
    }
    __syncwarp();

    // ---- phase A: rank + stage into smem in stable n-order ----
    // No per-round syncwarp: converged warp issues the all-lane LDS before
    // the predicated leader STS (same-array aliasing pins compiler order) —
    // same pattern as R4's proven-bit-exact scatter.
    const int*   __restrict__ vs = vr + seg * SEGSZ;
    const float* __restrict__ ps = pr + seg * SEGSZ;

#pragma unroll 4
    for (int r = 0; r < SEGSZ / 32; ++r) {
        int   g = vs[r * 32 + l];
        float p = ps[r * 32 + l];
        unsigned m = __match_any_sync(0xFFFFFFFFu, g);
        unsigned lr = __popc(m & lt);
        unsigned cur = s_lrun[g];
        unsigned slot = cur + lr;
        s_val[slot] = p;
        s_gid[slot] = (unsigned char)g;
        if (lr == 0u) s_lrun[g] = cur + __popc(m);
    }
    __syncwarp();

    // ---- phase B: linear sweep -> run-coalesced global stores ----
    float* __restrict__ dst = g_sorted + (long)b * Nn;
#pragma unroll 4
    for (int r = 0; r < SEGSZ / 32; ++r) {
        int s = r * 32 + l;
        int g = s_gid[s];
        dst[s_K[g] + s] = s_val[s];
    }
}

// ---------------- kernel 4: sequential fold (depth-4 ring pipeline) ------
__device__ __forceinline__ void fold8(float4* q, float& acc, float& mn, float& mx) {
#pragma unroll
    for (int j = 0; j < 8; ++j) {
        acc = __fadd_rn(acc, q[j].x);
        acc = __fadd_rn(acc, q[j].y);
        acc = __fadd_rn(acc, q[j].z);
        acc = __fadd_rn(acc, q[j].w);
        mn = fminf(mn, fminf(fminf(q[j].x, q[j].y), fminf(q[j].z, q[j].w)));
        mx = fmaxf(mx, fmaxf(fmaxf(q[j].x, q[j].y), fmaxf(q[j].z, q[j].w)));
    }
}

__device__ __forceinline__ void load8(float4* q, const float* p) {
#pragma unroll
    for (int j = 0; j < 8; ++j) q[j] = *(const float4*)(p + j * 4);
}

__global__ __launch_bounds__(32) void k_fold() {
    int gid = blockIdx.x * 32 + threadIdx.x;   // 0..8191
    int b = gid >> 8, g = gid & 255;

    unsigned cnt  = g_tot[b][g];
    const float* __restrict__ src = g_sorted + (long)b * Nn + g_base[b][g];

    float acc = 0.0f;
    float mn =  __int_as_float(0x7F800000);    // +inf
    float mx = -__int_as_float(0x7F800000);    // -inf

    unsigned i = 0;
    // scalar head until 16B aligned (order-preserving)
    while (i < cnt && ((((uintptr_t)(src + i)) & 15u) != 0u)) {
        float a = src[i];
        acc = __fadd_rn(acc, a);
        mn = fminf(mn, a); mx = fmaxf(mx, a);
        ++i;
    }

    // depth-4 ring: 32 LDG.128 in flight; folds strictly in batch order
    unsigned nb = (cnt - i) / 32;              // number of 32-elem batches
    float4 b0[8], b1[8], b2[8], b3[8];
    if (nb > 0) load8(b0, src + i);
    if (nb > 1) load8(b1, src + i + 32);
    if (nb > 2) load8(b2, src + i + 64);
    if (nb > 3) load8(b3, src + i + 96);

    unsigned bi = 0;
    for (; bi + 4 <= nb; bi += 4) {
        fold8(b0, acc, mn, mx);
        if (bi + 4 < nb) load8(b0, src + i + (bi + 4) * 32);
        fold8(b1, acc, mn, mx);
        if (bi + 5 < nb) load8(b1, src + i + (bi + 5) * 32);
        fold8(b2, acc, mn, mx);
        if (bi + 6 < nb) load8(b2, src + i + (bi + 6) * 32);
        fold8(b3, acc, mn, mx);
        if (bi + 7 < nb) load8(b3, src + i + (bi + 7) * 32);
    }
    unsigned rem = nb - bi;                    // 0..3, slots 0..2 in order
    if (rem >= 1) fold8(b0, acc, mn, mx);
    if (rem >= 2) fold8(b1, acc, mn, mx);
    if (rem >= 3) fold8(b2, acc, mn, mx);
    i += nb * 32;

    for (; i + 4 <= cnt; i += 4) {
        float4 q = *(const float4*)(src + i);
        acc = __fadd_rn(acc, q.x);
        acc = __fadd_rn(acc, q.y);
        acc = __fadd_rn(acc, q.z);
        acc = __fadd_rn(acc, q.w);
        mn = fminf(mn, fminf(fminf(q.x, q.y), fminf(q.z, q.w)));
        mx = fmaxf(mx, fmaxf(fmaxf(q.x, q.y), fmaxf(q.z, q.w)));
    }
    for (; i < cnt; ++i) {
        float a = src[i];
        acc = __fadd_rn(acc, a);
        mn = fminf(mn, a); mx = fmaxf(mx, a);
    }

    g_SMM[gid] = make_float4(acc, mn, mx, 0.0f);
}

// ---------------- kernel 5: sort + per-group affine params ---------------
__global__ __launch_bounds__(Gn) void k_params(const float* __restrict__ inp_means,
                                               const float* __restrict__ W) {
    __shared__ float skey[Gn];
    __shared__ int   sid[Gn];
    __shared__ float f0u[Gn];
    __shared__ float f1u[Gn];

    int b = blockIdx.x;
    int g = threadIdx.x;
    int o = b * Gn + g;

    float4 smm = g_SMM[o];
    unsigned cnt = g_tot[b][g];
    bool any = (cnt > 0u);
    float vsum = any ? smm.x : 0.0f;
    float mn = smm.y, mx = smm.z;

    float W0 = W[0], W1 = W[1];
    float vmean = __fdiv_rn(__fadd_rn(__fmul_rn(inp_means[o], W0),
                                      __fmul_rn(vsum, W1)),
                            __fadd_rn(W0, W1));

    skey[g] = vmean;
    sid[g]  = g;
    __syncthreads();

    // bitonic sort on (value, id) == jax stable argsort
    for (int k = 2; k <= Gn; k <<= 1) {
        for (int j = k >> 1; j > 0; j >>= 1) {
            int ixj = g ^ j;
            if (ixj > g) {
                float a = skey[g], c = skey[ixj];
                int ia = sid[g], ic = sid[ixj];
                bool up = ((g & k) == 0);
                bool gt = (a > c) || (a == c && ia > ic);
                if (gt == up) {
                    skey[g] = c; skey[ixj] = a;
                    sid[g] = ic; sid[ixj] = ia;
                }
            }
            __syncthreads();
        }
    }

    float vsr   = skey[g];
    float vprev = (g == 0)      ? vsr : skey[g - 1];
    float vnext = (g == Gn - 1) ? __fmul_rn(vsr, 2.0f) : skey[g + 1];
    float f0 = __fdiv_rn(__fadd_rn(vprev, vsr), 1.999f);
    float f1 = __fdiv_rn(__fadd_rn(vsr, vnext), 2.001f);
    f0u[sid[g]] = f0;
    f1u[sid[g]] = f1;
    __syncthreads();

    bool ns = (mn == mx);   // empty group: inf == -inf -> false (matches ref)

    float mn2, mx2, f02, f12;
    if (!any) { mn2 = 0.0f; mx2 = 1.0f; f02 = 0.0f; f12 = 0.0f; }
    else {
        mn2 = ns ? 0.0f : mn;
        mx2 = ns ? 1.0f : mx;
        f02 = ns ? 0.0f : f0u[g];
        f12 = ns ? 1.0f : f1u[g];
    }
    float rng = __fsub_rn(mx2, mn2);
    float df  = __fsub_rn(f12, f02);
    g_P[o] = make_float4(mn2, rng, df, f02);
}

// ---------------- kernel 6: elementwise apply ----------------------------
__device__ __forceinline__ float apply_one(float p, float4 P) {
    float t1  = __fsub_rn(p, P.x);
    float t2  = __fdiv_rn(t1, P.y);
    float t3  = __fmul_rn(t2, P.z);
    float tmp = __fadd_rn(t3, P.w);
    bool bad = bit_isnan(tmp) || bit_iszero(tmp);
    float den = bad ? 1.0f : tmp;
    float r;
    asm("rcp.approx.f32 %0, %1;" : "=f"(r) : "f"(den));
    float s = __fmul_rn(p, r);
    float scale = (bad || bit_nonfinite(s)) ? 0.0f : s;
    return __fmul_rn(p, scale);
}

__global__ __launch_bounds__(256) void k_apply(const float* __restrict__ pr,
                                               const int* __restrict__ vr,
                                               float* __restrict__ out) {
    __shared__ float4 sP[Gn];
    long base = (long)blockIdx.x * CHUNK;
    int b = blockIdx.x / (Nn / CHUNK);

    int t = threadIdx.x;
    sP[t] = g_P[b * Gn + t];
    __syncthreads();

    const float4* p4 = (const float4*)(pr + base);
    const int4*   v4 = (const int4*)(vr + base);
    float4*       o4 = (float4*)(out + base);

#pragma unroll 4
    for (int it = 0; it < CHUNK / 1024; ++it) {
        float4 p = p4[it * 256 + t];
        int4   v = v4[it * 256 + t];
        float4 r;
        r.x = apply_one(p.x, sP[v.x]);
        r.y = apply_one(p.y, sP[v.y]);
        r.z = apply_one(p.z, sP[v.z]);
        r.w = apply_one(p.w, sP[v.w]);
        o4[it * 256 + t] = r;
    }
}

// ---------------- launch --------------------------------------------------
extern "C" void kernel_launch(void* const* d_in, const int* in_sizes, int n_in,
                              void* d_out, int out_size) {
    const float* pr        = (const float*)d_in[0];
    const float* inp_means = (const float*)d_in[1];
    const int*   vr        = (const int*)d_in[2];
    const float* W         = (const float*)d_in[3];
    float* out = (float*)d_out;

    static int smem_set = 0;
    if (!smem_set) {
        cudaFuncSetAttribute(k_scatter, cudaFuncAttributeMaxDynamicSharedMemorySize,
                             SCAT_SMEM);
        smem_set = 1;
    }

    k_hist<<<NSEG / NWARP, 256>>>(vr);
    k_scan<<<Bn, Gn>>>();
    k_nop<<<1, 32>>>();                       // shifts ncu capture onto k_scatter
    k_scatter<<<NSEG / NWARP, 256, SCAT_SMEM>>>(pr, vr);
    k_fold<<<(Bn * Gn) / 32, 32>>>();
    k_params<<<Bn, Gn>>>(inp_means, W);
    k_apply<<<NBLK, 256>>>(pr, vr, out);
}

// round 15
// speedup vs baseline: 1.5578x; 1.0284x over previous
#include <cuda_runtime.h>
#include <math.h>
#include <stdint.h>

#define Bn 32
#define Nn 262144
#define Gn 256
#define SEGSZ 1024              // elements per warp-segment
#define SEGPB (Nn / SEGSZ)      // 256 segments per batch
#define NSEG (Bn * SEGPB)       // 8192 segments
#define NWARP 8                 // warps per block (hist/scatter)
#define CHUNK 16384
#define NBLK ((Bn * Nn) / CHUNK)   // 512

// ---------------- scratch (device globals; no allocation) ----------------
__device__ unsigned g_cnt[NSEG][Gn];   // counts -> within-batch exclusive prefix (after k_scan)
__device__ unsigned g_base[Bn][Gn];    // group base offset within batch
__device__ unsigned g_tot[Bn][Gn];     // group totals
__device__ float    g_sorted[Bn * Nn]; // stable-partitioned pr (n-order within group)
__device__ float4   g_SMM[Bn * Gn];    // per-group (sum, min, max, -)
__device__ float4   g_P[Bn * Gn];      // per-group (mn', rng, df, f0')

__device__ __forceinline__ bool bit_isnan(float f) {
    return (__float_as_uint(f) << 1) > 0xFF000000u;
}
__device__ __forceinline__ bool bit_iszero(float f) {
    return (__float_as_uint(f) << 1) == 0u;
}
__device__ __forceinline__ bool bit_nonfinite(float f) {
    return (__float_as_uint(f) << 1) >= 0xFF000000u;
}

// ---------------- kernel 1: per-segment histogram (warp-private) ---------
__global__ __launch_bounds__(256) void k_hist(const int* __restrict__ vr) {
    __shared__ unsigned s_h[NWARP][Gn];
    int t = threadIdx.x, w = t >> 5, l = t & 31;
    unsigned lt = (1u << l) - 1u;

#pragma unroll
    for (int i = l; i < Gn; i += 32) s_h[w][i] = 0u;
    __syncwarp();

    long seg = (long)blockIdx.x * NWARP + w;
    const int4* __restrict__ src = (const int4*)(vr + seg * SEGSZ);

#pragma unroll 2
    for (int r = 0; r < SEGSZ / 128; ++r) {
        int4 v = src[r * 32 + l];
        int gv[4] = {v.x, v.y, v.z, v.w};
#pragma unroll
        for (int e = 0; e < 4; ++e) {
            unsigned m = __match_any_sync(0xFFFFFFFFu, gv[e]);
            if ((m & lt) == 0u) s_h[w][gv[e]] += __popc(m);
        }
    }
    __syncwarp();

#pragma unroll
    for (int i = l; i < Gn; i += 32) g_cnt[seg][i] = s_h[w][i];
}

// ---------------- kernel 2: scans (per-batch) ----------------------------
__global__ __launch_bounds__(Gn) void k_scan() {
    int b = blockIdx.x;
    int g = threadIdx.x;

    unsigned run = 0;
#pragma unroll 8
    for (int s = 0; s < SEGPB; ++s) {
        int idx = b * SEGPB + s;
        unsigned c = g_cnt[idx][g];
        g_cnt[idx][g] = run;          // exclusive prefix within batch, per group
        run += c;
    }
    g_tot[b][g] = run;

    __shared__ unsigned sh[Gn];
    sh[g] = run;
    __syncthreads();
    for (int d = 1; d < Gn; d <<= 1) {
        unsigned x = (g >= d) ? sh[g - d] : 0u;
        __syncthreads();
        sh[g] += x;
        __syncthreads();
    }
    g_base[b][g] = sh[g] - run;       // exclusive scan over groups
}

// ---------------- dummy kernel: shifts ncu capture slot onto k_scatter ---
__global__ void k_nop() {}

// ---------------- kernel 3: stable scatter via smem reorder --------------
// per-warp: s_val 4KB + s_gid 1KB + s_lrun 1KB + s_K 1KB = 7KB; x8 = 56KB
#define SCAT_SMEM (NWARP * SEGSZ * 4 + NWARP * SEGSZ + NWARP * Gn * 4 + NWARP * Gn * 4)

__global__ __launch_bounds__(256) void k_scatter(const float* __restrict__ pr,
                                                 const int* __restrict__ vr) {
    extern __shared__ unsigned char sm[];
    int t = threadIdx.x, w = t >> 5, l = t & 31;
    unsigned lt = (1u << l) - 1u;

    float*         s_val  = (float*)sm + (long)w * SEGSZ;
    unsigned char* s_gid  = sm + NWARP * SEGSZ * 4 + w * SEGSZ;
    unsigned*      s_lrun = (unsigned*)(sm + NWARP * SEGSZ * 5) + w * Gn;
    unsigned*      s_K    = (unsigned*)(sm + NWARP * SEGSZ * 5 + NWARP * Gn * 4) + w * Gn;

    long seg = (long)blockIdx.x * NWARP + w;
    int b    = (int)(seg >> 8);       // seg / SEGPB (SEGPB = 256)
    int sidx = (int)(seg & (SEGPB - 1));
    bool last = (sidx == SEGPB - 1);

    // ---- phase 0: per-group local counts (prefix-row diff) + warp scan ----
    const uint4* preR  = (const uint4*)g_cnt[seg];
    const uint4* nxtR  = last ? (const uint4*)g_tot[b] : (const uint4*)g_cnt[seg + 1];
    const uint4* gbR   = (const uint4*)g_base[b];

    unsigned pre[8], cnt[8], gb[8];
#pragma unroll
    for (int h = 0; h < 2; ++h) {
        uint4 a = preR[l * 2 + h], c = nxtR[l * 2 + h], d = gbR[l * 2 + h];
        pre[h*4+0] = a.x; pre[h*4+1] = a.y; pre[h*4+2] = a.z; pre[h*4+3] = a.w;
        cnt[h*4+0] = c.x - a.x; cnt[h*4+1] = c.y - a.y;
        cnt[h*4+2] = c.z - a.z; cnt[h*4+3] = c.w - a.w;
        gb[h*4+0] = d.x; gb[h*4+1] = d.y; gb[h*4+2] = d.z; gb[h*4+3] = d.w;
    }
    unsigned lsum = 0;
#pragma unroll
    for (int k = 0; k < 8; ++k) lsum += cnt[k];
    unsigned sc = lsum;
#pragma unroll
    for (int d = 1; d < 32; d <<= 1) {
        unsigned v = __shfl_up_sync(0xFFFFFFFFu, sc, d);
        if (l >= d) sc += v;
    }
    unsigned running = sc - lsum;     // exclusive
#pragma unroll
    for (int k = 0; k < 8; ++k) {
        int g = l * 8 + k;
        s_lrun[g] = running;                       // lbase
        s_K[g]    = gb[k] + pre[k] - running;      // dest = K[g] + slot
        running  += cnt[k];
    }
    __syncwarp();

    // ---- phase A: rank + stage into smem in stable n-order ----
    const int*   __restrict__ vs = vr + seg * SEGSZ;
    const float* __restrict__ ps = pr + seg * SEGSZ;

#pragma unroll 4
    for (int r = 0; r < SEGSZ / 32; ++r) {
        int   g = vs[r * 32 + l];
        float p = ps[r * 32 + l];
        unsigned m = __match_any_sync(0xFFFFFFFFu, g);
        unsigned lr = __popc(m & lt);
        unsigned cur = s_lrun[g];
        unsigned slot = cur + lr;
        s_val[slot] = p;
        s_gid[slot] = (unsigned char)g;
        if (lr == 0u) s_lrun[g] = cur + __popc(m);
    }
    __syncwarp();

    // ---- phase B: linear sweep -> run-coalesced global stores ----
    float* __restrict__ dst = g_sorted + (long)b * Nn;
#pragma unroll 4
    for (int r = 0; r < SEGSZ / 32; ++r) {
        int s = r * 32 + l;
        int g = s_gid[s];
        dst[s_K[g] + s] = s_val[s];
    }
}

// ---------------- kernel 4: sequential fold (depth-4 ring pipeline) ------
__device__ __forceinline__ void fold8(float4* q, float& acc, float& mn, float& mx) {
#pragma unroll
    for (int j = 0; j < 8; ++j) {
        acc = __fadd_rn(acc, q[j].x);
        acc = __fadd_rn(acc, q[j].y);
        acc = __fadd_rn(acc, q[j].z);
        acc = __fadd_rn(acc, q[j].w);
        mn = fminf(mn, fminf(fminf(q[j].x, q[j].y), fminf(q[j].z, q[j].w)));
        mx = fmaxf(mx, fmaxf(fmaxf(q[j].x, q[j].y), fmaxf(q[j].z, q[j].w)));
    }
}

__device__ __forceinline__ void load8(float4* q, const float* p) {
#pragma unroll
    for (int j = 0; j < 8; ++j) q[j] = *(const float4*)(p + j * 4);
}

__global__ __launch_bounds__(32) void k_fold() {
    int gid = blockIdx.x * 32 + threadIdx.x;   // 0..8191
    int b = gid >> 8, g = gid & 255;

    unsigned cnt  = g_tot[b][g];
    const float* __restrict__ src = g_sorted + (long)b * Nn + g_base[b][g];

    float acc = 0.0f;
    float mn =  __int_as_float(0x7F800000);    // +inf
    float mx = -__int_as_float(0x7F800000);    // -inf

    unsigned i = 0;
    // scalar head until 16B aligned (order-preserving)
    while (i < cnt && ((((uintptr_t)(src + i)) & 15u) != 0u)) {
        float a = src[i];
        acc = __fadd_rn(acc, a);
        mn = fminf(mn, a); mx = fmaxf(mx, a);
        ++i;
    }

    // depth-4 ring: 32 LDG.128 in flight; folds strictly in batch order
    unsigned nb = (cnt - i) / 32;              // number of 32-elem batches
    float4 b0[8], b1[8], b2[8], b3[8];
    if (nb > 0) load8(b0, src + i);
    if (nb > 1) load8(b1, src + i + 32);
    if (nb > 2) load8(b2, src + i + 64);
    if (nb > 3) load8(b3, src + i + 96);

    unsigned bi = 0;
    for (; bi + 4 <= nb; bi += 4) {
        fold8(b0, acc, mn, mx);
        if (bi + 4 < nb) load8(b0, src + i + (bi + 4) * 32);
        fold8(b1, acc, mn, mx);
        if (bi + 5 < nb) load8(b1, src + i + (bi + 5) * 32);
        fold8(b2, acc, mn, mx);
        if (bi + 6 < nb) load8(b2, src + i + (bi + 6) * 32);
        fold8(b3, acc, mn, mx);
        if (bi + 7 < nb) load8(b3, src + i + (bi + 7) * 32);
    }
    unsigned rem = nb - bi;                    // 0..3, slots 0..2 in order
    if (rem >= 1) fold8(b0, acc, mn, mx);
    if (rem >= 2) fold8(b1, acc, mn, mx);
    if (rem >= 3) fold8(b2, acc, mn, mx);
    i += nb * 32;

    for (; i + 4 <= cnt; i += 4) {
        float4 q = *(const float4*)(src + i);
        acc = __fadd_rn(acc, q.x);
        acc = __fadd_rn(acc, q.y);
        acc = __fadd_rn(acc, q.z);
        acc = __fadd_rn(acc, q.w);
        mn = fminf(mn, fminf(fminf(q.x, q.y), fminf(q.z, q.w)));
        mx = fmaxf(mx, fmaxf(fmaxf(q.x, q.y), fmaxf(q.z, q.w)));
    }
    for (; i < cnt; ++i) {
        float a = src[i];
        acc = __fadd_rn(acc, a);
        mn = fminf(mn, a); mx = fmaxf(mx, a);
    }

    g_SMM[gid] = make_float4(acc, mn, mx, 0.0f);
}

// ---------------- kernel 5: sort + per-group affine params ---------------
__global__ __launch_bounds__(Gn) void k_params(const float* __restrict__ inp_means,
                                               const float* __restrict__ W) {
    __shared__ float skey[Gn];
    __shared__ int   sid[Gn];
    __shared__ float f0u[Gn];
    __shared__ float f1u[Gn];

    int b = blockIdx.x;
    int g = threadIdx.x;
    int o = b * Gn + g;

    float4 smm = g_SMM[o];
    unsigned cnt = g_tot[b][g];
    bool any = (cnt > 0u);
    float vsum = any ? smm.x : 0.0f;
    float mn = smm.y, mx = smm.z;

    float W0 = W[0], W1 = W[1];
    float vmean = __fdiv_rn(__fadd_rn(__fmul_rn(inp_means[o], W0),
                                      __fmul_rn(vsum, W1)),
                            __fadd_rn(W0, W1));

    skey[g] = vmean;
    sid[g]  = g;
    __syncthreads();

    // bitonic sort on (value, id) == jax stable argsort
    for (int k = 2; k <= Gn; k <<= 1) {
        for (int j = k >> 1; j > 0; j >>= 1) {
            int ixj = g ^ j;
            if (ixj > g) {
                float a = skey[g], c = skey[ixj];
                int ia = sid[g], ic = sid[ixj];
                bool up = ((g & k) == 0);
                bool gt = (a > c) || (a == c && ia > ic);
                if (gt == up) {
                    skey[g] = c; skey[ixj] = a;
                    sid[g] = ic; sid[ixj] = ia;
                }
            }
            __syncthreads();
        }
    }

    float vsr   = skey[g];
    float vprev = (g == 0)      ? vsr : skey[g - 1];
    float vnext = (g == Gn - 1) ? __fmul_rn(vsr, 2.0f) : skey[g + 1];
    float f0 = __fdiv_rn(__fadd_rn(vprev, vsr), 1.999f);
    float f1 = __fdiv_rn(__fadd_rn(vsr, vnext), 2.001f);
    f0u[sid[g]] = f0;
    f1u[sid[g]] = f1;
    __syncthreads();

    bool ns = (mn == mx);   // empty group: inf == -inf -> false (matches ref)

    float mn2, mx2, f02, f12;
    if (!any) { mn2 = 0.0f; mx2 = 1.0f; f02 = 0.0f; f12 = 0.0f; }
    else {
        mn2 = ns ? 0.0f : mn;
        mx2 = ns ? 1.0f : mx;
        f02 = ns ? 0.0f : f0u[g];
        f12 = ns ? 1.0f : f1u[g];
    }
    float rng = __fsub_rn(mx2, mn2);
    float df  = __fsub_rn(f12, f02);
    g_P[o] = make_float4(mn2, rng, df, f02);
}

// ---------------- kernel 6: elementwise apply ----------------------------
__device__ __forceinline__ float apply_one(float p, float4 P) {
    float t1  = __fsub_rn(p, P.x);
    float t2  = __fdiv_rn(t1, P.y);
    float t3  = __fmul_rn(t2, P.z);
    float tmp = __fadd_rn(t3, P.w);
    bool bad = bit_isnan(tmp) || bit_iszero(tmp);
    float den = bad ? 1.0f : tmp;
    float r;
    asm("rcp.approx.f32 %0, %1;" : "=f"(r) : "f"(den));
    float s = __fmul_rn(p, r);
    float scale = (bad || bit_nonfinite(s)) ? 0.0f : s;
    return __fmul_rn(p, scale);
}

__global__ __launch_bounds__(256) void k_apply(const float* __restrict__ pr,
                                               const int* __restrict__ vr,
                                               float* __restrict__ out) {
    __shared__ float4 sP[Gn];
    long base = (long)blockIdx.x * CHUNK;
    int b = blockIdx.x / (Nn / CHUNK);

    int t = threadIdx.x;
    sP[t] = g_P[b * Gn + t];
    __syncthreads();

    const float4* p4 = (const float4*)(pr + base);
    const int4*   v4 = (const int4*)(vr + base);
    float4*       o4 = (float4*)(out + base);

#pragma unroll 4
    for (int it = 0; it < CHUNK / 1024; ++it) {
        float4 p = p4[it * 256 + t];
        int4   v = v4[it * 256 + t];
        float4 r;
        r.x = apply_one(p.x, sP[v.x]);
        r.y = apply_one(p.y, sP[v.y]);
        r.z = apply_one(p.z, sP[v.z]);
        r.w = apply_one(p.w, sP[v.w]);
        o4[it * 256 + t] = r;
    }
}

// ---------------- launch --------------------------------------------------
extern "C" void kernel_launch(void* const* d_in, const int* in_sizes, int n_in,
                              void* d_out, int out_size) {
    const float* pr        = (const float*)d_in[0];
    const float* inp_means = (const float*)d_in[1];
    const int*   vr        = (const int*)d_in[2];
    const float* W         = (const float*)d_in[3];
    float* out = (float*)d_out;

    static int smem_set = 0;
    if (!smem_set) {
        cudaFuncSetAttribute(k_scatter, cudaFuncAttributeMaxDynamicSharedMemorySize,
                             SCAT_SMEM);
        smem_set = 1;
    }

    k_hist<<<NSEG / NWARP, 256>>>(vr);
    k_scan<<<Bn, Gn>>>();
    k_nop<<<1, 32>>>();                       // shifts ncu capture onto k_scatter
    k_scatter<<<NSEG / NWARP, 256, SCAT_SMEM>>>(pr, vr);
    k_fold<<<(Bn * Gn) / 32, 32>>>();
    k_params<<<Bn, Gn>>>(inp_means, W);
    k_apply<<<NBLK, 256>>>(pr, vr, out);
}

// round 16
// speedup vs baseline: 1.8771x; 1.2049x over previous
#include <cuda_runtime.h>
#include <math.h>
#include <stdint.h>

#define Bn 32
#define Nn 262144
#define Gn 256
#define SEGSZ 2048              // elements per warp-segment
#define SEGPB (Nn / SEGSZ)      // 128 segments per batch
#define NSEG (Bn * SEGPB)       // 4096 segments
#define NWARP 8                 // warps per block (hist/place)
#define CHUNK 16384
#define NBLK ((Bn * Nn) / CHUNK)   // 512

// ---------------- scratch (device globals; no allocation) ----------------
__device__ unsigned g_cnt[NSEG][Gn];   // counts -> within-batch exclusive prefix (after k_scan)
__device__ unsigned g_base[Bn][Gn];    // group base offset within batch
__device__ unsigned g_tot[Bn][Gn];     // group totals
__device__ unsigned g_rank[Bn * Nn];   // per-element packed (g | within-seg rank << 8)
__device__ float    g_sorted[Bn * Nn]; // stable-partitioned pr (n-order within group)
__device__ float4   g_SMM[Bn * Gn];    // per-group (sum, min, max, -)
__device__ float4   g_P[Bn * Gn];      // per-group (mn', rng, df, f0')

__device__ __forceinline__ bool bit_isnan(float f) {
    return (__float_as_uint(f) << 1) > 0xFF000000u;
}
__device__ __forceinline__ bool bit_iszero(float f) {
    return (__float_as_uint(f) << 1) == 0u;
}
__device__ __forceinline__ bool bit_nonfinite(float f) {
    return (__float_as_uint(f) << 1) >= 0xFF000000u;
}

// ---------------- kernel 1: hist + stable rank in ONE match pass ---------
// s_h[g] before update == count of g in earlier rounds == rank base
// (R9 k_sortlocal pattern, proven bit-exact; R14-proven race-free form).
__global__ __launch_bounds__(256) void k_hist(const int* __restrict__ vr) {
    __shared__ unsigned s_h[NWARP][Gn];
    int t = threadIdx.x, w = t >> 5, l = t & 31;
    unsigned lt = (1u << l) - 1u;

#pragma unroll
    for (int i = l; i < Gn; i += 32) s_h[w][i] = 0u;
    __syncwarp();

    long seg = (long)blockIdx.x * NWARP + w;
    const int* __restrict__ src = vr + seg * SEGSZ;
    unsigned* __restrict__ prk = g_rank + seg * SEGSZ;

#pragma unroll 4
    for (int r = 0; r < SEGSZ / 32; ++r) {
        int g = src[r * 32 + l];
        unsigned m = __match_any_sync(0xFFFFFFFFu, g);
        unsigned lr = __popc(m & lt);
        unsigned cur = s_h[w][g];
        prk[r * 32 + l] = (unsigned)g | ((cur + lr) << 8);
        if (lr == 0u) s_h[w][g] = cur + __popc(m);
    }
    __syncwarp();

#pragma unroll
    for (int i = l; i < Gn; i += 32) g_cnt[seg][i] = s_h[w][i];
}

// ---------------- kernel 2: scans (per-batch) ----------------------------
__global__ __launch_bounds__(Gn) void k_scan() {
    int b = blockIdx.x;
    int g = threadIdx.x;

    unsigned run = 0;
#pragma unroll 8
    for (int s = 0; s < SEGPB; ++s) {
        int idx = b * SEGPB + s;
        unsigned c = g_cnt[idx][g];
        g_cnt[idx][g] = run;          // exclusive prefix within batch, per group
        run += c;
    }
    g_tot[b][g] = run;

    __shared__ unsigned sh[Gn];
    sh[g] = run;
    __syncthreads();
    for (int d = 1; d < Gn; d <<= 1) {
        unsigned x = (g >= d) ? sh[g - d] : 0u;
        __syncthreads();
        sh[g] += x;
        __syncthreads();
    }
    g_base[b][g] = sh[g] - run;       // exclusive scan over groups
}

// ---------------- dummy kernel: shifts ncu capture slot onto k_place -----
__global__ void k_nop() {}

// ---------------- kernel 3: chain-free placement via smem staging --------
#define SCAT_SMEM (NWARP * SEGSZ * 4 + NWARP * SEGSZ + NWARP * Gn * 4 + NWARP * Gn * 4)

__global__ __launch_bounds__(256) void k_place(const float* __restrict__ pr) {
    extern __shared__ unsigned char sm[];
    int t = threadIdx.x, w = t >> 5, l = t & 31;

    float*         s_val = (float*)sm + (long)w * SEGSZ;
    unsigned char* s_gid = sm + NWARP * SEGSZ * 4 + w * SEGSZ;
    unsigned*      s_lb  = (unsigned*)(sm + NWARP * SEGSZ * 5) + w * Gn;
    unsigned*      s_K   = (unsigned*)(sm + NWARP * SEGSZ * 5 + NWARP * Gn * 4) + w * Gn;

    long seg = (long)blockIdx.x * NWARP + w;
    int b    = (int)(seg >> 7);       // seg / SEGPB
    int sidx = (int)(seg & (SEGPB - 1));
    bool last = (sidx == SEGPB - 1);

    // ---- phase 0: per-group local counts (prefix-row diff) + warp scan ----
    const uint4* preR  = (const uint4*)g_cnt[seg];
    const uint4* nxtR  = last ? (const uint4*)g_tot[b] : (const uint4*)g_cnt[seg + 1];
    const uint4* gbR   = (const uint4*)g_base[b];

    unsigned pre[8], cnt[8], gb[8];
#pragma unroll
    for (int h = 0; h < 2; ++h) {
        uint4 a = preR[l * 2 + h], c = nxtR[l * 2 + h], d = gbR[l * 2 + h];
        pre[h*4+0] = a.x; pre[h*4+1] = a.y; pre[h*4+2] = a.z; pre[h*4+3] = a.w;
        cnt[h*4+0] = c.x - a.x; cnt[h*4+1] = c.y - a.y;
        cnt[h*4+2] = c.z - a.z; cnt[h*4+3] = c.w - a.w;
        gb[h*4+0] = d.x; gb[h*4+1] = d.y; gb[h*4+2] = d.z; gb[h*4+3] = d.w;
    }
    unsigned lsum = 0;
#pragma unroll
    for (int k = 0; k < 8; ++k) lsum += cnt[k];
    unsigned sc = lsum;
#pragma unroll
    for (int d = 1; d < 32; d <<= 1) {
        unsigned v = __shfl_up_sync(0xFFFFFFFFu, sc, d);
        if (l >= d) sc += v;
    }
    unsigned running = sc - lsum;     // exclusive
#pragma unroll
    for (int k = 0; k < 8; ++k) {
        int g = l * 8 + k;
        s_lb[g] = running;                         // lbase (read-only after this)
        s_K[g]  = gb[k] + pre[k] - running;        // dest = K[g] + slot
        running += cnt[k];
    }
    __syncwarp();

    // ---- phase A: chain-free staging (rank precomputed in k_hist) ----
    const unsigned* __restrict__ rk = g_rank + seg * SEGSZ;
    const float*    __restrict__ ps = pr + seg * SEGSZ;

#pragma unroll 4
    for (int r = 0; r < SEGSZ / 32; ++r) {
        unsigned pk = rk[r * 32 + l];
        float p = ps[r * 32 + l];
        unsigned g = pk & 255u;
        unsigned slot = s_lb[g] + (pk >> 8);
        s_val[slot] = p;
        s_gid[slot] = (unsigned char)g;
    }
    __syncwarp();

    // ---- phase B: linear sweep -> run-coalesced global stores ----
    float* __restrict__ dst = g_sorted + (long)b * Nn;
#pragma unroll 4
    for (int r = 0; r < SEGSZ / 32; ++r) {
        int s = r * 32 + l;
        int g = s_gid[s];
        dst[s_K[g] + s] = s_val[s];
    }
}

// ---------------- kernel 4: sequential fold (depth-4 ring pipeline) ------
__device__ __forceinline__ void fold8(float4* q, float& acc, float& mn, float& mx) {
#pragma unroll
    for (int j = 0; j < 8; ++j) {
        acc = __fadd_rn(acc, q[j].x);
        acc = __fadd_rn(acc, q[j].y);
        acc = __fadd_rn(acc, q[j].z);
        acc = __fadd_rn(acc, q[j].w);
        mn = fminf(mn, fminf(fminf(q[j].x, q[j].y), fminf(q[j].z, q[j].w)));
        mx = fmaxf(mx, fmaxf(fmaxf(q[j].x, q[j].y), fmaxf(q[j].z, q[j].w)));
    }
}

__device__ __forceinline__ void load8(float4* q, const float* p) {
#pragma unroll
    for (int j = 0; j < 8; ++j) q[j] = *(const float4*)(p + j * 4);
}

__global__ __launch_bounds__(32) void k_fold() {
    int gid = blockIdx.x * 32 + threadIdx.x;   // 0..8191
    int b = gid >> 8, g = gid & 255;

    unsigned cnt  = g_tot[b][g];
    const float* __restrict__ src = g_sorted + (long)b * Nn + g_base[b][g];

    float acc = 0.0f;
    float mn =  __int_as_float(0x7F800000);    // +inf
    float mx = -__int_as_float(0x7F800000);    // -inf

    unsigned i = 0;
    // scalar head until 16B aligned (order-preserving)
    while (i < cnt && ((((uintptr_t)(src + i)) & 15u) != 0u)) {
        float a = src[i];
        acc = __fadd_rn(acc, a);
        mn = fminf(mn, a); mx = fmaxf(mx, a);
        ++i;
    }

    // depth-4 ring: 32 LDG.128 in flight; folds strictly in batch order
    unsigned nb = (cnt - i) / 32;              // number of 32-elem batches
    float4 b0[8], b1[8], b2[8], b3[8];
    if (nb > 0) load8(b0, src + i);
    if (nb > 1) load8(b1, src + i + 32);
    if (nb > 2) load8(b2, src + i + 64);
    if (nb > 3) load8(b3, src + i + 96);

    unsigned bi = 0;
    for (; bi + 4 <= nb; bi += 4) {
        fold8(b0, acc, mn, mx);
        if (bi + 4 < nb) load8(b0, src + i + (bi + 4) * 32);
        fold8(b1, acc, mn, mx);
        if (bi + 5 < nb) load8(b1, src + i + (bi + 5) * 32);
        fold8(b2, acc, mn, mx);
        if (bi + 6 < nb) load8(b2, src + i + (bi + 6) * 32);
        fold8(b3, acc, mn, mx);
        if (bi + 7 < nb) load8(b3, src + i + (bi + 7) * 32);
    }
    unsigned rem = nb - bi;                    // 0..3, slots 0..2 in order
    if (rem >= 1) fold8(b0, acc, mn, mx);
    if (rem >= 2) fold8(b1, acc, mn, mx);
    if (rem >= 3) fold8(b2, acc, mn, mx);
    i += nb * 32;

    for (; i + 4 <= cnt; i += 4) {
        float4 q = *(const float4*)(src + i);
        acc = __fadd_rn(acc, q.x);
        acc = __fadd_rn(acc, q.y);
        acc = __fadd_rn(acc, q.z);
        acc = __fadd_rn(acc, q.w);
        mn = fminf(mn, fminf(fminf(q.x, q.y), fminf(q.z, q.w)));
        mx = fmaxf(mx, fmaxf(fmaxf(q.x, q.y), fmaxf(q.z, q.w)));
    }
    for (; i < cnt; ++i) {
        float a = src[i];
        acc = __fadd_rn(acc, a);
        mn = fminf(mn, a); mx = fmaxf(mx, a);
    }

    g_SMM[gid] = make_float4(acc, mn, mx, 0.0f);
}

// ---------------- kernel 5: sort + per-group affine params ---------------
__global__ __launch_bounds__(Gn) void k_params(const float* __restrict__ inp_means,
                                               const float* __restrict__ W) {
    __shared__ float skey[Gn];
    __shared__ int   sid[Gn];
    __shared__ float f0u[Gn];
    __shared__ float f1u[Gn];

    int b = blockIdx.x;
    int g = threadIdx.x;
    int o = b * Gn + g;

    float4 smm = g_SMM[o];
    unsigned cnt = g_tot[b][g];
    bool any = (cnt > 0u);
    float vsum = any ? smm.x : 0.0f;
    float mn = smm.y, mx = smm.z;

    float W0 = W[0], W1 = W[1];
    float vmean = __fdiv_rn(__fadd_rn(__fmul_rn(inp_means[o], W0),
                                      __fmul_rn(vsum, W1)),
                            __fadd_rn(W0, W1));

    skey[g] = vmean;
    sid[g]  = g;
    __syncthreads();

    // bitonic sort on (value, id) == jax stable argsort
    for (int k = 2; k <= Gn; k <<= 1) {
        for (int j = k >> 1; j > 0; j >>= 1) {
            int ixj = g ^ j;
            if (ixj > g) {
                float a = skey[g], c = skey[ixj];
                int ia = sid[g], ic = sid[ixj];
                bool up = ((g & k) == 0);
                bool gt = (a > c) || (a == c && ia > ic);
                if (gt == up) {
                    skey[g] = c; skey[ixj] = a;
                    sid[g] = ic; sid[ixj] = ia;
                }
            }
            __syncthreads();
        }
    }

    float vsr   = skey[g];
    float vprev = (g == 0)      ? vsr : skey[g - 1];
    float vnext = (g == Gn - 1) ? __fmul_rn(vsr, 2.0f) : skey[g + 1];
    float f0 = __fdiv_rn(__fadd_rn(vprev, vsr), 1.999f);
    float f1 = __fdiv_rn(__fadd_rn(vsr, vnext), 2.001f);
    f0u[sid[g]] = f0;
    f1u[sid[g]] = f1;
    __syncthreads();

    bool ns = (mn == mx);   // empty group: inf == -inf -> false (matches ref)

    float mn2, mx2, f02, f12;
    if (!any) { mn2 = 0.0f; mx2 = 1.0f; f02 = 0.0f; f12 = 0.0f; }
    else {
        mn2 = ns ? 0.0f : mn;
        mx2 = ns ? 1.0f : mx;
        f02 = ns ? 0.0f : f0u[g];
        f12 = ns ? 1.0f : f1u[g];
    }
    float rng = __fsub_rn(mx2, mn2);
    float df  = __fsub_rn(f12, f02);
    g_P[o] = make_float4(mn2, rng, df, f02);
}

// ---------------- kernel 6: elementwise apply ----------------------------
__device__ __forceinline__ float apply_one(float p, float4 P) {
    float t1  = __fsub_rn(p, P.x);
    float t2  = __fdiv_rn(t1, P.y);
    float t3  = __fmul_rn(t2, P.z);
    float tmp = __fadd_rn(t3, P.w);
    bool bad = bit_isnan(tmp) || bit_iszero(tmp);
    float den = bad ? 1.0f : tmp;
    float r;
    asm("rcp.approx.f32 %0, %1;" : "=f"(r) : "f"(den));
    float s = __fmul_rn(p, r);
    float scale = (bad || bit_nonfinite(s)) ? 0.0f : s;
    return __fmul_rn(p, scale);
}

__global__ __launch_bounds__(256) void k_apply(const float* __restrict__ pr,
                                               const int* __restrict__ vr,
                                               float* __restrict__ out) {
    __shared__ float4 sP[Gn];
    long base = (long)blockIdx.x * CHUNK;
    int b = blockIdx.x / (Nn / CHUNK);

    int t = threadIdx.x;
    sP[t] = g_P[b * Gn + t];
    __syncthreads();

    const float4* p4 = (const float4*)(pr + base);
    const int4*   v4 = (const int4*)(vr + base);
    float4*       o4 = (float4*)(out + base);

#pragma unroll 4
    for (int it = 0; it < CHUNK / 1024; ++it) {
        float4 p = p4[it * 256 + t];
        int4   v = v4[it * 256 + t];
        float4 r;
        r.x = apply_one(p.x, sP[v.x]);
        r.y = apply_one(p.y, sP[v.y]);
        r.z = apply_one(p.z, sP[v.z]);
        r.w = apply_one(p.w, sP[v.w]);
        o4[it * 256 + t] = r;
    }
}

// ---------------- launch --------------------------------------------------
extern "C" void kernel_launch(void* const* d_in, const int* in_sizes, int n_in,
                              void* d_out, int out_size) {
    const float* pr        = (const float*)d_in[0];
    const float* inp_means = (const float*)d_in[1];
    const int*   vr        = (const int*)d_in[2];
    const float* W         = (const float*)d_in[3];
    float* out = (float*)d_out;

    static int smem_set = 0;
    if (!smem_set) {
        cudaFuncSetAttribute(k_place, cudaFuncAttributeMaxDynamicSharedMemorySize,
                             SCAT_SMEM);
        smem_set = 1;
    }

    k_hist<<<NSEG / NWARP, 256>>>(vr);
    k_scan<<<Bn, Gn>>>();
    k_nop<<<1, 32>>>();                       // shifts ncu capture onto k_place
    k_place<<<NSEG / NWARP, 256, SCAT_SMEM>>>(pr);
    k_fold<<<(Bn * Gn) / 32, 32>>>();
    k_params<<<Bn, Gn>>>(inp_means, W);
    k_apply<<<NBLK, 256>>>(pr, vr, out);
}

// round 17
// speedup vs baseline: 1.8825x; 1.0029x over previous
#include <cuda_runtime.h>
#include <math.h>
#include <stdint.h>

#define Bn 32
#define Nn 262144
#define Gn 256
#define SEGSZ 2048              // elements per warp-segment
#define SEGPB (Nn / SEGSZ)      // 128 segments per batch
#define NSEG (Bn * SEGPB)       // 4096 segments
#define NWARP 8                 // warps per block (hist/place)
#define CHUNK 8192
#define NBLK ((Bn * Nn) / CHUNK)   // 1024

// ---------------- scratch (device globals; no allocation) ----------------
__device__ unsigned g_cnt[NSEG][Gn];   // counts -> within-batch exclusive prefix (after k_scan)
__device__ unsigned g_base[Bn][Gn];    // group base offset within batch
__device__ unsigned g_tot[Bn][Gn];     // group totals
__device__ unsigned g_rank[Bn * Nn];   // per-element packed (g | within-seg rank << 8)
__device__ float    g_sorted[Bn * Nn]; // stable-partitioned pr (n-order within group)
__device__ float4   g_SMM[Bn * Gn];    // per-group (sum, min, max, -)
__device__ float4   g_P[Bn * Gn];      // per-group (mn', rng, df, f0')

__device__ __forceinline__ bool bit_isnan(float f) {
    return (__float_as_uint(f) << 1) > 0xFF000000u;
}
__device__ __forceinline__ bool bit_iszero(float f) {
    return (__float_as_uint(f) << 1) == 0u;
}
__device__ __forceinline__ bool bit_nonfinite(float f) {
    return (__float_as_uint(f) << 1) >= 0xFF000000u;
}

// ---------------- kernel 1: hist + stable rank in ONE match pass ---------
__global__ __launch_bounds__(256) void k_hist(const int* __restrict__ vr) {
    __shared__ unsigned s_h[NWARP][Gn];
    int t = threadIdx.x, w = t >> 5, l = t & 31;
    unsigned lt = (1u << l) - 1u;

#pragma unroll
    for (int i = l; i < Gn; i += 32) s_h[w][i] = 0u;
    __syncwarp();

    long seg = (long)blockIdx.x * NWARP + w;
    const int* __restrict__ src = vr + seg * SEGSZ;
    unsigned* __restrict__ prk = g_rank + seg * SEGSZ;

#pragma unroll 4
    for (int r = 0; r < SEGSZ / 32; ++r) {
        int g = src[r * 32 + l];
        unsigned m = __match_any_sync(0xFFFFFFFFu, g);
        unsigned lr = __popc(m & lt);
        unsigned cur = s_h[w][g];
        prk[r * 32 + l] = (unsigned)g | ((cur + lr) << 8);
        if (lr == 0u) s_h[w][g] = cur + __popc(m);
    }
    __syncwarp();

#pragma unroll
    for (int i = l; i < Gn; i += 32) g_cnt[seg][i] = s_h[w][i];
}

// ---------------- kernel 2: scans (per-batch) ----------------------------
__global__ __launch_bounds__(Gn) void k_scan() {
    int b = blockIdx.x;
    int g = threadIdx.x;

    unsigned run = 0;
#pragma unroll 16
    for (int s = 0; s < SEGPB; ++s) {
        int idx = b * SEGPB + s;
        unsigned c = g_cnt[idx][g];
        g_cnt[idx][g] = run;          // exclusive prefix within batch, per group
        run += c;
    }
    g_tot[b][g] = run;

    __shared__ unsigned sh[Gn];
    sh[g] = run;
    __syncthreads();
    for (int d = 1; d < Gn; d <<= 1) {
        unsigned x = (g >= d) ? sh[g - d] : 0u;
        __syncthreads();
        sh[g] += x;
        __syncthreads();
    }
    g_base[b][g] = sh[g] - run;       // exclusive scan over groups
}

// ---------------- dummy kernel (x3): shifts ncu capture onto k_hist ------
__global__ void k_nop() {}

// ---------------- kernel 3: chain-free placement via smem staging --------
#define SCAT_SMEM (NWARP * SEGSZ * 4 + NWARP * SEGSZ + NWARP * Gn * 4 + NWARP * Gn * 4)

__global__ __launch_bounds__(256) void k_place(const float* __restrict__ pr) {
    extern __shared__ unsigned char sm[];
    int t = threadIdx.x, w = t >> 5, l = t & 31;

    float*         s_val = (float*)sm + (long)w * SEGSZ;
    unsigned char* s_gid = sm + NWARP * SEGSZ * 4 + w * SEGSZ;
    unsigned*      s_lb  = (unsigned*)(sm + NWARP * SEGSZ * 5) + w * Gn;
    unsigned*      s_K   = (unsigned*)(sm + NWARP * SEGSZ * 5 + NWARP * Gn * 4) + w * Gn;

    long seg = (long)blockIdx.x * NWARP + w;
    int b    = (int)(seg >> 7);       // seg / SEGPB
    int sidx = (int)(seg & (SEGPB - 1));
    bool last = (sidx == SEGPB - 1);

    // ---- phase 0: per-group local counts (prefix-row diff) + warp scan ----
    const uint4* preR  = (const uint4*)g_cnt[seg];
    const uint4* nxtR  = last ? (const uint4*)g_tot[b] : (const uint4*)g_cnt[seg + 1];
    const uint4* gbR   = (const uint4*)g_base[b];

    unsigned pre[8], cnt[8], gb[8];
#pragma unroll
    for (int h = 0; h < 2; ++h) {
        uint4 a = preR[l * 2 + h], c = nxtR[l * 2 + h], d = gbR[l * 2 + h];
        pre[h*4+0] = a.x; pre[h*4+1] = a.y; pre[h*4+2] = a.z; pre[h*4+3] = a.w;
        cnt[h*4+0] = c.x - a.x; cnt[h*4+1] = c.y - a.y;
        cnt[h*4+2] = c.z - a.z; cnt[h*4+3] = c.w - a.w;
        gb[h*4+0] = d.x; gb[h*4+1] = d.y; gb[h*4+2] = d.z; gb[h*4+3] = d.w;
    }
    unsigned lsum = 0;
#pragma unroll
    for (int k = 0; k < 8; ++k) lsum += cnt[k];
    unsigned sc = lsum;
#pragma unroll
    for (int d = 1; d < 32; d <<= 1) {
        unsigned v = __shfl_up_sync(0xFFFFFFFFu, sc, d);
        if (l >= d) sc += v;
    }
    unsigned running = sc - lsum;     // exclusive
#pragma unroll
    for (int k = 0; k < 8; ++k) {
        int g = l * 8 + k;
        s_lb[g] = running;                         // lbase (read-only after this)
        s_K[g]  = gb[k] + pre[k] - running;        // dest = K[g] + slot
        running += cnt[k];
    }
    __syncwarp();

    // ---- phase A: chain-free staging (rank precomputed in k_hist) ----
    const unsigned* __restrict__ rk = g_rank + seg * SEGSZ;
    const float*    __restrict__ ps = pr + seg * SEGSZ;

#pragma unroll 4
    for (int r = 0; r < SEGSZ / 32; ++r) {
        unsigned pk = rk[r * 32 + l];
        float p = ps[r * 32 + l];
        unsigned g = pk & 255u;
        unsigned slot = s_lb[g] + (pk >> 8);
        s_val[slot] = p;
        s_gid[slot] = (unsigned char)g;
    }
    __syncwarp();

    // ---- phase B: linear sweep -> run-coalesced global stores ----
    float* __restrict__ dst = g_sorted + (long)b * Nn;
#pragma unroll 4
    for (int r = 0; r < SEGSZ / 32; ++r) {
        int s = r * 32 + l;
        int g = s_gid[s];
        dst[s_K[g] + s] = s_val[s];
    }
}

// ---------------- kernel 4: sequential fold (depth-4 ring pipeline) ------
__device__ __forceinline__ void fold8(float4* q, float& acc, float& mn, float& mx) {
#pragma unroll
    for (int j = 0; j < 8; ++j) {
        acc = __fadd_rn(acc, q[j].x);
        acc = __fadd_rn(acc, q[j].y);
        acc = __fadd_rn(acc, q[j].z);
        acc = __fadd_rn(acc, q[j].w);
        mn = fminf(mn, fminf(fminf(q[j].x, q[j].y), fminf(q[j].z, q[j].w)));
        mx = fmaxf(mx, fmaxf(fmaxf(q[j].x, q[j].y), fmaxf(q[j].z, q[j].w)));
    }
}

__device__ __forceinline__ void load8(float4* q, const float* p) {
#pragma unroll
    for (int j = 0; j < 8; ++j) q[j] = *(const float4*)(p + j * 4);
}

__global__ __launch_bounds__(32) void k_fold() {
    int gid = blockIdx.x * 32 + threadIdx.x;   // 0..8191
    int b = gid >> 8, g = gid & 255;

    unsigned cnt  = g_tot[b][g];
    const float* __restrict__ src = g_sorted + (long)b * Nn + g_base[b][g];

    float acc = 0.0f;
    float mn =  __int_as_float(0x7F800000);    // +inf
    float mx = -__int_as_float(0x7F800000);    // -inf

    unsigned i = 0;
    // scalar head until 16B aligned (order-preserving)
    while (i < cnt && ((((uintptr_t)(src + i)) & 15u) != 0u)) {
        float a = src[i];
        acc = __fadd_rn(acc, a);
        mn = fminf(mn, a); mx = fmaxf(mx, a);
        ++i;
    }

    // depth-4 ring: 32 LDG.128 in flight; folds strictly in batch order
    unsigned nb = (cnt - i) / 32;              // number of 32-elem batches
    float4 b0[8], b1[8], b2[8], b3[8];
    if (nb > 0) load8(b0, src + i);
    if (nb > 1) load8(b1, src + i + 32);
    if (nb > 2) load8(b2, src + i + 64);
    if (nb > 3) load8(b3, src + i + 96);

    unsigned bi = 0;
    for (; bi + 4 <= nb; bi += 4) {
        fold8(b0, acc, mn, mx);
        if (bi + 4 < nb) load8(b0, src + i + (bi + 4) * 32);
        fold8(b1, acc, mn, mx);
        if (bi + 5 < nb) load8(b1, src + i + (bi + 5) * 32);
        fold8(b2, acc, mn, mx);
        if (bi + 6 < nb) load8(b2, src + i + (bi + 6) * 32);
        fold8(b3, acc, mn, mx);
        if (bi + 7 < nb) load8(b3, src + i + (bi + 7) * 32);
    }
    unsigned rem = nb - bi;                    // 0..3, slots 0..2 in order
    if (rem >= 1) fold8(b0, acc, mn, mx);
    if (rem >= 2) fold8(b1, acc, mn, mx);
    if (rem >= 3) fold8(b2, acc, mn, mx);
    i += nb * 32;

    for (; i + 4 <= cnt; i += 4) {
        float4 q = *(const float4*)(src + i);
        acc = __fadd_rn(acc, q.x);
        acc = __fadd_rn(acc, q.y);
        acc = __fadd_rn(acc, q.z);
        acc = __fadd_rn(acc, q.w);
        mn = fminf(mn, fminf(fminf(q.x, q.y), fminf(q.z, q.w)));
        mx = fmaxf(mx, fmaxf(fmaxf(q.x, q.y), fmaxf(q.z, q.w)));
    }
    for (; i < cnt; ++i) {
        float a = src[i];
        acc = __fadd_rn(acc, a);
        mn = fminf(mn, a); mx = fmaxf(mx, a);
    }

    g_SMM[gid] = make_float4(acc, mn, mx, 0.0f);
}

// ---------------- kernel 5: sort + per-group affine params ---------------
__global__ __launch_bounds__(Gn) void k_params(const float* __restrict__ inp_means,
                                               const float* __restrict__ W) {
    __shared__ float skey[Gn];
    __shared__ int   sid[Gn];
    __shared__ float f0u[Gn];
    __shared__ float f1u[Gn];

    int b = blockIdx.x;
    int g = threadIdx.x;
    int o = b * Gn + g;

    float4 smm = g_SMM[o];
    unsigned cnt = g_tot[b][g];
    bool any = (cnt > 0u);
    float vsum = any ? smm.x : 0.0f;
    float mn = smm.y, mx = smm.z;

    float W0 = W[0], W1 = W[1];
    float vmean = __fdiv_rn(__fadd_rn(__fmul_rn(inp_means[o], W0),
                                      __fmul_rn(vsum, W1)),
                            __fadd_rn(W0, W1));

    skey[g] = vmean;
    sid[g]  = g;
    __syncthreads();

    // bitonic sort on (value, id) == jax stable argsort
    for (int k = 2; k <= Gn; k <<= 1) {
        for (int j = k >> 1; j > 0; j >>= 1) {
            int ixj = g ^ j;
            if (ixj > g) {
                float a = skey[g], c = skey[ixj];
                int ia = sid[g], ic = sid[ixj];
                bool up = ((g & k) == 0);
                bool gt = (a > c) || (a == c && ia > ic);
                if (gt == up) {
                    skey[g] = c; skey[ixj] = a;
                    sid[g] = ic; sid[ixj] = ia;
                }
            }
            __syncthreads();
        }
    }

    float vsr   = skey[g];
    float vprev = (g == 0)      ? vsr : skey[g - 1];
    float vnext = (g == Gn - 1) ? __fmul_rn(vsr, 2.0f) : skey[g + 1];
    float f0 = __fdiv_rn(__fadd_rn(vprev, vsr), 1.999f);
    float f1 = __fdiv_rn(__fadd_rn(vsr, vnext), 2.001f);
    f0u[sid[g]] = f0;
    f1u[sid[g]] = f1;
    __syncthreads();

    bool ns = (mn == mx);   // empty group: inf == -inf -> false (matches ref)

    float mn2, mx2, f02, f12;
    if (!any) { mn2 = 0.0f; mx2 = 1.0f; f02 = 0.0f; f12 = 0.0f; }
    else {
        mn2 = ns ? 0.0f : mn;
        mx2 = ns ? 1.0f : mx;
        f02 = ns ? 0.0f : f0u[g];
        f12 = ns ? 1.0f : f1u[g];
    }
    float rng = __fsub_rn(mx2, mn2);
    float df  = __fsub_rn(f12, f02);
    g_P[o] = make_float4(mn2, rng, df, f02);
}

// ---------------- kernel 6: elementwise apply ----------------------------
__device__ __forceinline__ float apply_one(float p, float4 P) {
    float t1  = __fsub_rn(p, P.x);
    float t2  = __fdiv_rn(t1, P.y);
    float t3  = __fmul_rn(t2, P.z);
    float tmp = __fadd_rn(t3, P.w);
    bool bad = bit_isnan(tmp) || bit_iszero(tmp);
    float den = bad ? 1.0f : tmp;
    float r;
    asm("rcp.approx.f32 %0, %1;" : "=f"(r) : "f"(den));
    float s = __fmul_rn(p, r);
    float scale = (bad || bit_nonfinite(s)) ? 0.0f : s;
    return __fmul_rn(p, scale);
}

__global__ __launch_bounds__(256) void k_apply(const float* __restrict__ pr,
                                               const int* __restrict__ vr,
                                               float* __restrict__ out) {
    __shared__ float4 sP[Gn];
    long base = (long)blockIdx.x * CHUNK;
    int b = blockIdx.x / (Nn / CHUNK);

    int t = threadIdx.x;
    sP[t] = g_P[b * Gn + t];
    __syncthreads();

    const float4* p4 = (const float4*)(pr + base);
    const int4*   v4 = (const int4*)(vr + base);
    float4*       o4 = (float4*)(out + base);

#pragma unroll 4
    for (int it = 0; it < CHUNK / 1024; ++it) {
        float4 p = p4[it * 256 + t];
        int4   v = v4[it * 256 + t];
        float4 r;
        r.x = apply_one(p.x, sP[v.x]);
        r.y = apply_one(p.y, sP[v.y]);
        r.z = apply_one(p.z, sP[v.z]);
        r.w = apply_one(p.w, sP[v.w]);
        o4[it * 256 + t] = r;
    }
}

// ---------------- launch --------------------------------------------------
extern "C" void kernel_launch(void* const* d_in, const int* in_sizes, int n_in,
                              void* d_out, int out_size) {
    const float* pr        = (const float*)d_in[0];
    const float* inp_means = (const float*)d_in[1];
    const int*   vr        = (const int*)d_in[2];
    const float* W         = (const float*)d_in[3];
    float* out = (float*)d_out;

    static int smem_set = 0;
    if (!smem_set) {
        cudaFuncSetAttribute(k_place, cudaFuncAttributeMaxDynamicSharedMemorySize,
                             SCAT_SMEM);
        smem_set = 1;
    }

    k_nop<<<1, 32>>>();                       // slot shift: ncu captures index 3
    k_nop<<<1, 32>>>();
    k_nop<<<1, 32>>>();
    k_hist<<<NSEG / NWARP, 256>>>(vr);        // <- profiled this round
    k_scan<<<Bn, Gn>>>();
    k_place<<<NSEG / NWARP, 256, SCAT_SMEM>>>(pr);
    k_fold<<<(Bn * Gn) / 32, 32>>>();
    k_params<<<Bn, Gn>>>(inp_means, W);
    k_apply<<<NBLK, 256>>>(pr, vr, out);
}